// round 10
// baseline (speedup 1.0000x reference)
#include <cuda_runtime.h>
#include <cuda_bf16.h>
#include <cstdint>

#define NN   50000
#define NE   600000
#define NT   (NE + NN)     // edges + self loops = 650000
#define D    128

// ---------------- device scratch (static, no runtime alloc) ----------------
// All features live as bf16 hi/lo pairs; fp32 only for the final output buffer.
__device__ __nv_bfloat16 g_Fh[2][(size_t)NN * D];
__device__ __nv_bfloat16 g_Fl[2][(size_t)NN * D];
__device__ __nv_bfloat16 g_P1h[(size_t)NN * D];
__device__ __nv_bfloat16 g_P1l[(size_t)NN * D];
__device__ __nv_bfloat16 g_P2h[(size_t)NN * D];
__device__ __nv_bfloat16 g_P2l[(size_t)NN * D];
__device__ float         g_Yf[(size_t)NN * D];     // final embedding (pred input)
__device__ int2  g_colew[NT];            // packed {col, bitcast(weight)}
__device__ int   g_rowptr[NN + 1];
__device__ int   g_deg[NN];              // zero-init at load; scan self-resets
__device__ int   g_cursor[NN];
__device__ float g_dinv[NN];
// Folded W (W0-W2, -W1, 2*W2) as bf16 hi/lo, transposed: [layer][n(128)][k(384)]
__device__ __nv_bfloat16 g_Whi[3 * 128 * 384];
__device__ __nv_bfloat16 g_Wlo[3 * 128 * 384];

// ---------------- helpers ----------------
__device__ __forceinline__ uint32_t pack2(float a, float b) {
    __nv_bfloat162 h = __floats2bfloat162_rn(a, b);
    return *reinterpret_cast<uint32_t*>(&h);
}
// split fp32x4 -> bf16 hi/lo uint2 pair
__device__ __forceinline__ void split4(float4 v, uint2& hv, uint2& lv) {
    __nv_bfloat16 h0 = __float2bfloat16_rn(v.x);
    __nv_bfloat16 h1 = __float2bfloat16_rn(v.y);
    __nv_bfloat16 h2 = __float2bfloat16_rn(v.z);
    __nv_bfloat16 h3 = __float2bfloat16_rn(v.w);
    hv = make_uint2(pack2(__bfloat162float(h0), __bfloat162float(h1)),
                    pack2(__bfloat162float(h2), __bfloat162float(h3)));
    lv = make_uint2(pack2(v.x - __bfloat162float(h0), v.y - __bfloat162float(h1)),
                    pack2(v.z - __bfloat162float(h2), v.w - __bfloat162float(h3)));
}
// rebuild fp32x4 from hi/lo uint2
__device__ __forceinline__ float4 rb4(uint2 h, uint2 l) {
    float2 a = __bfloat1622float2(*reinterpret_cast<__nv_bfloat162*>(&h.x));
    float2 b = __bfloat1622float2(*reinterpret_cast<__nv_bfloat162*>(&h.y));
    float2 c = __bfloat1622float2(*reinterpret_cast<__nv_bfloat162*>(&l.x));
    float2 d = __bfloat1622float2(*reinterpret_cast<__nv_bfloat162*>(&l.y));
    return make_float4(a.x + c.x, a.y + c.y, b.x + d.x, b.y + d.y);
}

#define CP16(daddr, gptr) \
    asm volatile("cp.async.cg.shared.global [%0], [%1], 16;" \
        :: "r"(daddr), "l"(gptr))
#define CP_COMMIT() asm volatile("cp.async.commit_group;" ::: "memory")
#define CP_WAIT(n)  asm volatile("cp.async.wait_group %0;" :: "n"(n) : "memory")

// ---------------- fused prep: count degrees | input linear | W fold ----------------
#define NB_COUNT ((NE + 255) / 256)               // 2344
#define NB_FEAT  ((NN * (D / 4) + 255) / 256)     // 6250
#define NB_WPREP ((3 * 384 * 128 + 255) / 256)    // 576
#define NB_PREP  (NB_COUNT + NB_FEAT + NB_WPREP)

__global__ void prep_kernel(const int* __restrict__ dst,
                            const float* __restrict__ w,
                            const float* __restrict__ lw,
                            const float* __restrict__ lb,
                            const float* __restrict__ cheb_ws) {
    int b = blockIdx.x;
    int tid = threadIdx.x;
    if (b < NB_COUNT) {
        int e = b * 256 + tid;
        if (e < NE) atomicAdd(&g_deg[dst[e]], 1);
    } else if (b < NB_COUNT + NB_FEAT) {
        int i = (b - NB_COUNT) * 256 + tid;
        if (i >= NN * (D / 4)) return;
        int v  = i >> 5;
        int d4 = i & 31;
        float s = __ldg(w + v);
        float4 a = __ldg((const float4*)lw + d4);
        float4 bb = __ldg((const float4*)lb + d4);
        float4 r;
        r.x = fmaf(s, a.x, bb.x); r.y = fmaf(s, a.y, bb.y);
        r.z = fmaf(s, a.z, bb.z); r.w = fmaf(s, a.w, bb.w);
        uint2 hv, lv;
        split4(r, hv, lv);
        *(uint2*)(g_Fh[0] + (size_t)i * 4) = hv;
        *(uint2*)(g_Fl[0] + (size_t)i * 4) = lv;
    } else {
        int i = (b - NB_COUNT - NB_FEAT) * 256 + tid;
        if (i >= 3 * 384 * 128) return;
        int l   = i / (384 * 128);
        int rem = i % (384 * 128);
        int k = rem >> 7;
        int n = rem & 127;
        int seg = k >> 7;
        int kin = k & 127;
        const float* WL0 = cheb_ws + (size_t)l * 384 * 128;
        float wv;
        if (seg == 0)      wv = __ldg(WL0 + (size_t)k * 128 + n) - __ldg(WL0 + (size_t)(256 + kin) * 128 + n);
        else if (seg == 1) wv = -__ldg(WL0 + (size_t)k * 128 + n);
        else               wv = 2.0f * __ldg(WL0 + (size_t)k * 128 + n);
        __nv_bfloat16 h = __float2bfloat16_rn(wv);
        size_t o = ((size_t)l * 128 + n) * 384 + k;
        g_Whi[o] = h;
        g_Wlo[o] = __float2bfloat16_rn(wv - __bfloat162float(h));
    }
}

// ---------------- CSR: single-block scan (smem-staged, self-resetting) --------
__global__ void scan_kernel() {
    extern __shared__ int ssm[];            // NN ints
    __shared__ int part[1024];
    const int T = 1024;
    const int CHUNK = (NN + T - 1) / T;     // 49
    int tid = threadIdx.x;

    for (int i = tid; i < NN; i += T) {
        ssm[i] = g_deg[i] + 1;              // +1 self loop
        g_deg[i] = 0;
        g_cursor[i] = 0;
    }
    __syncthreads();

    int start = tid * CHUNK;
    int end = start + CHUNK; if (end > NN) end = NN;
    int s = 0;
    for (int i = start; i < end; ++i) s += ssm[i];
    part[tid] = s;
    __syncthreads();
    for (int off = 1; off < T; off <<= 1) {
        int v = (tid >= off) ? part[tid - off] : 0;
        __syncthreads();
        part[tid] += v;
        __syncthreads();
    }
    int run = part[tid] - s;
    for (int i = start; i < end; ++i) {
        int v = ssm[i];
        ssm[i] = run;
        run += v;
    }
    __syncthreads();
    int total = part[T - 1];
    for (int i = tid; i < NN; i += T) {
        int rp = ssm[i];
        g_rowptr[i] = rp;
        int nxt = (i + 1 < NN) ? ssm[i + 1] : total;
        g_dinv[i] = rsqrtf((float)(nxt - rp));
    }
    if (tid == 0) g_rowptr[NN] = total;
}

__global__ void scatter_kernel(const int* __restrict__ src, const int* __restrict__ dst) {
    int e = blockIdx.x * blockDim.x + threadIdx.x;
    if (e >= NT) return;
    int s, d;
    if (e < NE) { s = src[e]; d = dst[e]; }
    else        { s = d = e - NE; }
    int pos = g_rowptr[d] + atomicAdd(&g_cursor[d], 1);
    g_colew[pos] = make_int2(s, __float_as_int(g_dinv[s] * g_dinv[d]));
}

// ---------------- SpMM: out = A_norm @ X, bf16 hi/lo in and out ----------------
__global__ void spmm_kernel(int mode, int flip) {
    const __nv_bfloat16 *Xh, *Xl;
    if (mode == 0) { Xh = g_Fh[flip]; Xl = g_Fl[flip]; }
    else           { Xh = g_P1h;      Xl = g_P1l; }

    int warp = (blockIdx.x * blockDim.x + threadIdx.x) >> 5;
    if (warp >= NN) return;
    int lane = threadIdx.x & 31;
    int beg = g_rowptr[warp];
    int end = g_rowptr[warp + 1];

    float4 acc = make_float4(0.f, 0.f, 0.f, 0.f);
    int p = beg;
    for (; p + 3 < end; p += 4) {
        int2 e0 = __ldg(g_colew + p);
        int2 e1 = __ldg(g_colew + p + 1);
        int2 e2 = __ldg(g_colew + p + 2);
        int2 e3 = __ldg(g_colew + p + 3);
        uint2 h0 = __ldg((const uint2*)(Xh + (size_t)e0.x * D) + lane);
        uint2 l0 = __ldg((const uint2*)(Xl + (size_t)e0.x * D) + lane);
        uint2 h1 = __ldg((const uint2*)(Xh + (size_t)e1.x * D) + lane);
        uint2 l1 = __ldg((const uint2*)(Xl + (size_t)e1.x * D) + lane);
        uint2 h2 = __ldg((const uint2*)(Xh + (size_t)e2.x * D) + lane);
        uint2 l2 = __ldg((const uint2*)(Xl + (size_t)e2.x * D) + lane);
        uint2 h3 = __ldg((const uint2*)(Xh + (size_t)e3.x * D) + lane);
        uint2 l3 = __ldg((const uint2*)(Xl + (size_t)e3.x * D) + lane);
        float4 x0 = rb4(h0, l0);
        float4 x1 = rb4(h1, l1);
        float4 x2 = rb4(h2, l2);
        float4 x3 = rb4(h3, l3);
        float w0 = __int_as_float(e0.y);
        float w1 = __int_as_float(e1.y);
        float w2 = __int_as_float(e2.y);
        float w3 = __int_as_float(e3.y);
        acc.x = fmaf(w0, x0.x, acc.x); acc.y = fmaf(w0, x0.y, acc.y);
        acc.z = fmaf(w0, x0.z, acc.z); acc.w = fmaf(w0, x0.w, acc.w);
        acc.x = fmaf(w1, x1.x, acc.x); acc.y = fmaf(w1, x1.y, acc.y);
        acc.z = fmaf(w1, x1.z, acc.z); acc.w = fmaf(w1, x1.w, acc.w);
        acc.x = fmaf(w2, x2.x, acc.x); acc.y = fmaf(w2, x2.y, acc.y);
        acc.z = fmaf(w2, x2.z, acc.z); acc.w = fmaf(w2, x2.w, acc.w);
        acc.x = fmaf(w3, x3.x, acc.x); acc.y = fmaf(w3, x3.y, acc.y);
        acc.z = fmaf(w3, x3.z, acc.z); acc.w = fmaf(w3, x3.w, acc.w);
    }
    for (; p < end; ++p) {
        int2 e0 = __ldg(g_colew + p);
        float w0 = __int_as_float(e0.y);
        uint2 h0 = __ldg((const uint2*)(Xh + (size_t)e0.x * D) + lane);
        uint2 l0 = __ldg((const uint2*)(Xl + (size_t)e0.x * D) + lane);
        float4 x0 = rb4(h0, l0);
        acc.x = fmaf(w0, x0.x, acc.x); acc.y = fmaf(w0, x0.y, acc.y);
        acc.z = fmaf(w0, x0.z, acc.z); acc.w = fmaf(w0, x0.w, acc.w);
    }

    uint2 hv, lv;
    split4(acc, hv, lv);
    size_t eo = (size_t)warp * D + lane * 4;
    if (mode == 0) {
        *(uint2*)(g_P1h + eo) = hv;
        *(uint2*)(g_P1l + eo) = lv;
    } else {
        *(uint2*)(g_P2h + eo) = hv;
        *(uint2*)(g_P2l + eo) = lv;
    }
}

// ======================= mma.sync bf16 GEMM (3-term split) =======================
// Y = relu(X0*W0' + P1*W1' + P2*W2' + b); all operands pre-split bf16 hi/lo.
// 8 warps, warp tile 64x32, m16n8k16. 6 chunks of K=64, double-buffered cp.async.
// Layers 0,1 emit bf16 hi/lo only; layer 2 emits fp32 (pred input).

#define ROW_W     36
#define BUF_W     (128 * ROW_W)
#define BUF_BYTES (BUF_W * 4)             // 18432
#define CH_BYTES  (4 * BUF_BYTES)         // 73728 (Ah,Al,Bh,Bl)
#define GSMEM     (2 * CH_BYTES)          // 147456 dynamic smem

__device__ __forceinline__ void mma_bf16(float* acc,
                                         uint32_t a0, uint32_t a1, uint32_t a2, uint32_t a3,
                                         uint32_t b0, uint32_t b1) {
    asm volatile(
        "mma.sync.aligned.m16n8k16.row.col.f32.bf16.bf16.f32 "
        "{%0,%1,%2,%3}, {%4,%5,%6,%7}, {%8,%9}, {%0,%1,%2,%3};"
        : "+f"(acc[0]), "+f"(acc[1]), "+f"(acc[2]), "+f"(acc[3])
        : "r"(a0), "r"(a1), "r"(a2), "r"(a3), "r"(b0), "r"(b1));
}

__device__ __forceinline__ void issue_chunk(
    uint32_t bb,
    const __nv_bfloat16* __restrict__ Xh, const __nv_bfloat16* __restrict__ Xl,
    const __nv_bfloat16* __restrict__ WH, const __nv_bfloat16* __restrict__ WL,
    int row0, int kk, int kbase, int tid)
{
#pragma unroll
    for (int i = 0; i < 4; ++i) {
        int idx = tid + i * 256;
        int r = idx >> 3, f = idx & 7;
        int grow = row0 + r; if (grow >= NN) grow = NN - 1;
        CP16(bb + (uint32_t)(r * ROW_W + f * 4) * 4,
             Xh + (size_t)grow * D + kk + f * 8);
    }
#pragma unroll
    for (int i = 0; i < 4; ++i) {
        int idx = tid + i * 256;
        int r = idx >> 3, f = idx & 7;
        int grow = row0 + r; if (grow >= NN) grow = NN - 1;
        CP16(bb + BUF_BYTES + (uint32_t)(r * ROW_W + f * 4) * 4,
             Xl + (size_t)grow * D + kk + f * 8);
    }
#pragma unroll
    for (int i = 0; i < 4; ++i) {
        int idx = tid + i * 256;
        int n = idx >> 3, f = idx & 7;
        CP16(bb + 2 * BUF_BYTES + (uint32_t)(n * ROW_W + f * 4) * 4,
             WH + (size_t)n * 384 + kbase + f * 8);
    }
#pragma unroll
    for (int i = 0; i < 4; ++i) {
        int idx = tid + i * 256;
        int n = idx >> 3, f = idx & 7;
        CP16(bb + 3 * BUF_BYTES + (uint32_t)(n * ROW_W + f * 4) * 4,
             WL + (size_t)n * 384 + kbase + f * 8);
    }
}

__global__ __launch_bounds__(256, 1)
void gemm_mma_kernel(int layer, const float* __restrict__ bias, int flip) {
    extern __shared__ uint32_t dsm[];
    uint32_t sbase = (uint32_t)__cvta_generic_to_shared(dsm);

    const __nv_bfloat16* AH0 = g_Fh[flip];
    const __nv_bfloat16* AL0 = g_Fl[flip];
    __nv_bfloat16* Yh = g_Fh[flip ^ 1];
    __nv_bfloat16* Yl = g_Fl[flip ^ 1];
    const __nv_bfloat16* WH = g_Whi + (size_t)layer * 128 * 384;
    const __nv_bfloat16* WL = g_Wlo + (size_t)layer * 128 * 384;
    bool last = (layer == 2);

    int tid = threadIdx.x;
    int wid = tid >> 5;
    int lane = tid & 31;
    int g   = lane >> 2;
    int tig = lane & 3;
    int row0 = blockIdx.x * 128;

    int m0w = (wid >> 2) * 64;
    int n0w = (wid & 3) * 32;

    float acc[4][4][4];
#pragma unroll
    for (int mi = 0; mi < 4; ++mi)
#pragma unroll
        for (int ni = 0; ni < 4; ++ni)
#pragma unroll
            for (int q = 0; q < 4; ++q) acc[mi][ni][q] = 0.f;

    issue_chunk(sbase, AH0, AL0, WH, WL, row0, 0, 0, tid);
    CP_COMMIT();

    for (int c = 0; c < 6; ++c) {
        if (c < 5) {
            int nc = c + 1;
            int srcI = nc >> 1, kk = (nc & 1) * 64;
            const __nv_bfloat16* Xh = (srcI == 0) ? AH0 : ((srcI == 1) ? g_P1h : g_P2h);
            const __nv_bfloat16* Xl = (srcI == 0) ? AL0 : ((srcI == 1) ? g_P1l : g_P2l);
            issue_chunk(sbase + (uint32_t)(nc & 1) * CH_BYTES,
                        Xh, Xl, WH, WL, row0, kk, srcI * 128 + kk, tid);
            CP_COMMIT();
            CP_WAIT(1);
        } else {
            CP_WAIT(0);
        }
        __syncthreads();

        const uint32_t* Ah = dsm + (size_t)(c & 1) * (4 * BUF_W);
        const uint32_t* Al = Ah + BUF_W;
        const uint32_t* Bh = Ah + 2 * BUF_W;
        const uint32_t* Bl = Ah + 3 * BUF_W;

#pragma unroll
        for (int ks = 0; ks < 4; ++ks) {
            int kw = ks * 8;
            uint32_t ah[4][4], al[4][4], bh[4][2], bl[4][2];
#pragma unroll
            for (int mi = 0; mi < 4; ++mi) {
                const uint32_t* ph = Ah + (m0w + mi * 16 + g) * ROW_W + kw + tig;
                const uint32_t* pl = Al + (m0w + mi * 16 + g) * ROW_W + kw + tig;
                ah[mi][0] = ph[0];             al[mi][0] = pl[0];
                ah[mi][1] = ph[8 * ROW_W];     al[mi][1] = pl[8 * ROW_W];
                ah[mi][2] = ph[4];             al[mi][2] = pl[4];
                ah[mi][3] = ph[8 * ROW_W + 4]; al[mi][3] = pl[8 * ROW_W + 4];
            }
#pragma unroll
            for (int ni = 0; ni < 4; ++ni) {
                const uint32_t* ph = Bh + (n0w + ni * 8 + g) * ROW_W + kw + tig;
                const uint32_t* pl = Bl + (n0w + ni * 8 + g) * ROW_W + kw + tig;
                bh[ni][0] = ph[0]; bh[ni][1] = ph[4];
                bl[ni][0] = pl[0]; bl[ni][1] = pl[4];
            }
#pragma unroll
            for (int mi = 0; mi < 4; ++mi)
#pragma unroll
                for (int ni = 0; ni < 4; ++ni) {
                    mma_bf16(acc[mi][ni], ah[mi][0], ah[mi][1], ah[mi][2], ah[mi][3],
                             bh[ni][0], bh[ni][1]);
                    mma_bf16(acc[mi][ni], ah[mi][0], ah[mi][1], ah[mi][2], ah[mi][3],
                             bl[ni][0], bl[ni][1]);
                    mma_bf16(acc[mi][ni], al[mi][0], al[mi][1], al[mi][2], al[mi][3],
                             bh[ni][0], bh[ni][1]);
                }
        }
        __syncthreads();
    }

    // ---- epilogue: + bias, relu; layers 0/1 -> bf16 hi/lo, layer 2 -> fp32 ----
#pragma unroll
    for (int mi = 0; mi < 4; ++mi) {
        int r0 = row0 + m0w + mi * 16 + g;
        int r1 = r0 + 8;
#pragma unroll
        for (int ni = 0; ni < 4; ++ni) {
            int c = n0w + ni * 8 + 2 * tig;
            float2 bb = *(const float2*)(bias + c);
            if (r0 < NN) {
                float vx = fmaxf(acc[mi][ni][0] + bb.x, 0.f);
                float vy = fmaxf(acc[mi][ni][1] + bb.y, 0.f);
                if (last) {
                    *(float2*)(g_Yf + (size_t)r0 * D + c) = make_float2(vx, vy);
                } else {
                    __nv_bfloat16 h0 = __float2bfloat16_rn(vx);
                    __nv_bfloat16 h1 = __float2bfloat16_rn(vy);
                    *(uint32_t*)(Yh + (size_t)r0 * D + c) =
                        pack2(__bfloat162float(h0), __bfloat162float(h1));
                    *(uint32_t*)(Yl + (size_t)r0 * D + c) =
                        pack2(vx - __bfloat162float(h0), vy - __bfloat162float(h1));
                }
            }
            if (r1 < NN) {
                float vx = fmaxf(acc[mi][ni][2] + bb.x, 0.f);
                float vy = fmaxf(acc[mi][ni][3] + bb.y, 0.f);
                if (last) {
                    *(float2*)(g_Yf + (size_t)r1 * D + c) = make_float2(vx, vy);
                } else {
                    __nv_bfloat16 h0 = __float2bfloat16_rn(vx);
                    __nv_bfloat16 h1 = __float2bfloat16_rn(vy);
                    *(uint32_t*)(Yh + (size_t)r1 * D + c) =
                        pack2(__bfloat162float(h0), __bfloat162float(h1));
                    *(uint32_t*)(Yl + (size_t)r1 * D + c) =
                        pack2(vx - __bfloat162float(h0), vy - __bfloat162float(h1));
                }
            }
        }
    }
}

// ---------------- prediction head ----------------
__global__ void pred_kernel(const float* __restrict__ pw,
                            const float* __restrict__ pb,
                            float* __restrict__ out) {
    int warp = (blockIdx.x * blockDim.x + threadIdx.x) >> 5;
    if (warp >= NN) return;
    int lane = threadIdx.x & 31;
    float4 e = ((const float4*)(g_Yf + (size_t)warp * D))[lane];
    float4 p = __ldg((const float4*)pw + lane);
    float s = e.x * p.x + e.y * p.y + e.z * p.z + e.w * p.w;
#pragma unroll
    for (int o = 16; o; o >>= 1) s += __shfl_xor_sync(0xffffffffu, s, o);
    if (lane == 0) out[warp] = s + __ldg(pb);
}

// ---------------- host launch ----------------
extern "C" void kernel_launch(void* const* d_in, const int* in_sizes, int n_in,
                              void* d_out, int out_size) {
    const float* weights = (const float*)d_in[0];
    const int*   src     = (const int*)d_in[1];
    const int*   dst     = (const int*)d_in[2];
    const float* lin_w   = (const float*)d_in[3];
    const float* lin_b   = (const float*)d_in[4];
    const float* cheb_ws = (const float*)d_in[5];
    const float* cheb_bs = (const float*)d_in[6];
    const float* pred_w  = (const float*)d_in[7];
    const float* pred_b  = (const float*)d_in[8];
    float* out = (float*)d_out;

    cudaFuncSetAttribute(gemm_mma_kernel,
                         cudaFuncAttributeMaxDynamicSharedMemorySize, GSMEM);
    cudaFuncSetAttribute(scan_kernel,
                         cudaFuncAttributeMaxDynamicSharedMemorySize, NN * 4);

    // fused count | feat | wprep, then scan, then scatter
    prep_kernel   <<<NB_PREP, 256>>>(dst, weights, lin_w, lin_b, cheb_ws);
    scan_kernel   <<<1, 1024, NN * 4>>>();
    scatter_kernel<<<(NT + 255) / 256, 256>>>(src, dst);

    const int spmm_blocks = (NN * 32 + 255) / 256;   // one warp per node
    const int gemm_blocks = (NN + 127) / 128;        // 391

    for (int l = 0; l < 3; ++l) {
        int flip = l & 1;
        spmm_kernel<<<spmm_blocks, 256>>>(0, flip);   // P1 = A~ X0
        spmm_kernel<<<spmm_blocks, 256>>>(1, flip);   // P2 = A~ P1
        gemm_mma_kernel<<<gemm_blocks, 256, GSMEM>>>(
            l, cheb_bs + (size_t)l * 128, flip);
        // inter-layer leaky_relu(relu(x)) == relu(x): no-op, skipped
    }

    pred_kernel<<<spmm_blocks, 256>>>(pred_w, pred_b, out);
}

// round 11
// speedup vs baseline: 1.0620x; 1.0620x over previous
#include <cuda_runtime.h>
#include <cuda_bf16.h>
#include <cstdint>

#define NN   50000
#define NE   600000
#define NT   (NE + NN)     // edges + self loops = 650000
#define D    128

// ---------------- device scratch (static, no runtime alloc) ----------------
// fp32 features for SpMM/pred; bf16 hi/lo mirrors for GEMM A operand.
__device__ float         g_Ff[2][(size_t)NN * D];
__device__ __nv_bfloat16 g_Fh[2][(size_t)NN * D];
__device__ __nv_bfloat16 g_Fl[2][(size_t)NN * D];
__device__ float         g_P1f[(size_t)NN * D];
__device__ __nv_bfloat16 g_P1h[(size_t)NN * D];
__device__ __nv_bfloat16 g_P1l[(size_t)NN * D];
__device__ __nv_bfloat16 g_P2h[(size_t)NN * D];
__device__ __nv_bfloat16 g_P2l[(size_t)NN * D];
__device__ int2  g_colew[NT];            // packed {col*D, bitcast(weight)}
__device__ int   g_rowptr[NN + 1];
__device__ int   g_deg[NN];              // zero-init at load; scan self-resets
__device__ int   g_cursor[NN];
__device__ float g_dinv[NN];
// Folded W (W0-W2, -W1, 2*W2) as bf16 hi/lo, transposed: [layer][n(128)][k(384)]
__device__ __nv_bfloat16 g_Whi[3 * 128 * 384];
__device__ __nv_bfloat16 g_Wlo[3 * 128 * 384];

// ---------------- helpers ----------------
__device__ __forceinline__ uint32_t pack2(float a, float b) {
    __nv_bfloat162 h = __floats2bfloat162_rn(a, b);
    return *reinterpret_cast<uint32_t*>(&h);
}
__device__ __forceinline__ void split4(float4 v, uint2& hv, uint2& lv) {
    __nv_bfloat16 h0 = __float2bfloat16_rn(v.x);
    __nv_bfloat16 h1 = __float2bfloat16_rn(v.y);
    __nv_bfloat16 h2 = __float2bfloat16_rn(v.z);
    __nv_bfloat16 h3 = __float2bfloat16_rn(v.w);
    hv = make_uint2(pack2(__bfloat162float(h0), __bfloat162float(h1)),
                    pack2(__bfloat162float(h2), __bfloat162float(h3)));
    lv = make_uint2(pack2(v.x - __bfloat162float(h0), v.y - __bfloat162float(h1)),
                    pack2(v.z - __bfloat162float(h2), v.w - __bfloat162float(h3)));
}

#define CP16(daddr, gptr) \
    asm volatile("cp.async.cg.shared.global [%0], [%1], 16;" \
        :: "r"(daddr), "l"(gptr))
#define CP_COMMIT() asm volatile("cp.async.commit_group;" ::: "memory")
#define CP_WAIT(n)  asm volatile("cp.async.wait_group %0;" :: "n"(n) : "memory")

// ---------------- fused prep: count degrees | input linear | W fold ----------------
#define NB_COUNT ((NE + 255) / 256)               // 2344
#define NB_FEAT  ((NN * (D / 4) + 255) / 256)     // 6250
#define NB_WPREP ((3 * 384 * 128 + 255) / 256)    // 576
#define NB_PREP  (NB_COUNT + NB_FEAT + NB_WPREP)

__global__ void prep_kernel(const int* __restrict__ dst,
                            const float* __restrict__ w,
                            const float* __restrict__ lw,
                            const float* __restrict__ lb,
                            const float* __restrict__ cheb_ws) {
    int b = blockIdx.x;
    int tid = threadIdx.x;
    if (b < NB_COUNT) {
        int e = b * 256 + tid;
        if (e < NE) atomicAdd(&g_deg[dst[e]], 1);
    } else if (b < NB_COUNT + NB_FEAT) {
        int i = (b - NB_COUNT) * 256 + tid;
        if (i >= NN * (D / 4)) return;
        int v  = i >> 5;
        int d4 = i & 31;
        float s = __ldg(w + v);
        float4 a = __ldg((const float4*)lw + d4);
        float4 bb = __ldg((const float4*)lb + d4);
        float4 r;
        r.x = fmaf(s, a.x, bb.x); r.y = fmaf(s, a.y, bb.y);
        r.z = fmaf(s, a.z, bb.z); r.w = fmaf(s, a.w, bb.w);
        ((float4*)g_Ff[0])[i] = r;
        uint2 hv, lv;
        split4(r, hv, lv);
        *(uint2*)(g_Fh[0] + (size_t)i * 4) = hv;
        *(uint2*)(g_Fl[0] + (size_t)i * 4) = lv;
    } else {
        int i = (b - NB_COUNT - NB_FEAT) * 256 + tid;
        if (i >= 3 * 384 * 128) return;
        int l   = i / (384 * 128);
        int rem = i % (384 * 128);
        int k = rem >> 7;
        int n = rem & 127;
        int seg = k >> 7;
        int kin = k & 127;
        const float* WL0 = cheb_ws + (size_t)l * 384 * 128;
        float wv;
        if (seg == 0)      wv = __ldg(WL0 + (size_t)k * 128 + n) - __ldg(WL0 + (size_t)(256 + kin) * 128 + n);
        else if (seg == 1) wv = -__ldg(WL0 + (size_t)k * 128 + n);
        else               wv = 2.0f * __ldg(WL0 + (size_t)k * 128 + n);
        __nv_bfloat16 h = __float2bfloat16_rn(wv);
        size_t o = ((size_t)l * 128 + n) * 384 + k;
        g_Whi[o] = h;
        g_Wlo[o] = __float2bfloat16_rn(wv - __bfloat162float(h));
    }
}

// ---------------- CSR: single-block scan (smem-staged, self-resetting) --------
__global__ void scan_kernel() {
    extern __shared__ int ssm[];            // NN ints
    __shared__ int part[1024];
    const int T = 1024;
    const int CHUNK = (NN + T - 1) / T;     // 49
    int tid = threadIdx.x;

    for (int i = tid; i < NN; i += T) {
        ssm[i] = g_deg[i] + 1;              // +1 self loop
        g_deg[i] = 0;
        g_cursor[i] = 0;
    }
    __syncthreads();

    int start = tid * CHUNK;
    int end = start + CHUNK; if (end > NN) end = NN;
    int s = 0;
    for (int i = start; i < end; ++i) s += ssm[i];
    part[tid] = s;
    __syncthreads();
    for (int off = 1; off < T; off <<= 1) {
        int v = (tid >= off) ? part[tid - off] : 0;
        __syncthreads();
        part[tid] += v;
        __syncthreads();
    }
    int run = part[tid] - s;
    for (int i = start; i < end; ++i) {
        int v = ssm[i];
        ssm[i] = run;
        run += v;
    }
    __syncthreads();
    int total = part[T - 1];
    for (int i = tid; i < NN; i += T) {
        int rp = ssm[i];
        g_rowptr[i] = rp;
        int nxt = (i + 1 < NN) ? ssm[i + 1] : total;
        g_dinv[i] = rsqrtf((float)(nxt - rp));
    }
    if (tid == 0) g_rowptr[NN] = total;
}

__global__ void scatter_kernel(const int* __restrict__ src, const int* __restrict__ dst) {
    int e = blockIdx.x * blockDim.x + threadIdx.x;
    if (e >= NT) return;
    int s, d;
    if (e < NE) { s = src[e]; d = dst[e]; }
    else        { s = d = e - NE; }
    int pos = g_rowptr[d] + atomicAdd(&g_cursor[d], 1);
    g_colew[pos] = make_int2(s * D, __float_as_int(g_dinv[s] * g_dinv[d]));
}

// ---------------- SpMM: out = A_norm @ X (fp32 gather, minimal issue) ----------
__global__ void spmm_kernel(int mode, int flip) {
    const float* __restrict__ X = (mode == 0) ? g_Ff[flip] : g_P1f;

    int warp = (blockIdx.x * blockDim.x + threadIdx.x) >> 5;
    if (warp >= NN) return;
    int lane = threadIdx.x & 31;
    int beg = g_rowptr[warp];
    int end = g_rowptr[warp + 1];

    const float* Xl4 = X + lane * 4;       // lane-fixed base; edge offset pre-scaled

    float4 acc = make_float4(0.f, 0.f, 0.f, 0.f);
    int p = beg;
    for (; p + 3 < end; p += 4) {
        int2 e0 = __ldg(g_colew + p);
        int2 e1 = __ldg(g_colew + p + 1);
        int2 e2 = __ldg(g_colew + p + 2);
        int2 e3 = __ldg(g_colew + p + 3);
        float4 x0 = *(const float4*)(Xl4 + e0.x);
        float4 x1 = *(const float4*)(Xl4 + e1.x);
        float4 x2 = *(const float4*)(Xl4 + e2.x);
        float4 x3 = *(const float4*)(Xl4 + e3.x);
        float w0 = __int_as_float(e0.y);
        float w1 = __int_as_float(e1.y);
        float w2 = __int_as_float(e2.y);
        float w3 = __int_as_float(e3.y);
        acc.x = fmaf(w0, x0.x, acc.x); acc.y = fmaf(w0, x0.y, acc.y);
        acc.z = fmaf(w0, x0.z, acc.z); acc.w = fmaf(w0, x0.w, acc.w);
        acc.x = fmaf(w1, x1.x, acc.x); acc.y = fmaf(w1, x1.y, acc.y);
        acc.z = fmaf(w1, x1.z, acc.z); acc.w = fmaf(w1, x1.w, acc.w);
        acc.x = fmaf(w2, x2.x, acc.x); acc.y = fmaf(w2, x2.y, acc.y);
        acc.z = fmaf(w2, x2.z, acc.z); acc.w = fmaf(w2, x2.w, acc.w);
        acc.x = fmaf(w3, x3.x, acc.x); acc.y = fmaf(w3, x3.y, acc.y);
        acc.z = fmaf(w3, x3.z, acc.z); acc.w = fmaf(w3, x3.w, acc.w);
    }
    for (; p < end; ++p) {
        int2 e0 = __ldg(g_colew + p);
        float w0 = __int_as_float(e0.y);
        float4 x0 = *(const float4*)(Xl4 + e0.x);
        acc.x = fmaf(w0, x0.x, acc.x); acc.y = fmaf(w0, x0.y, acc.y);
        acc.z = fmaf(w0, x0.z, acc.z); acc.w = fmaf(w0, x0.w, acc.w);
    }

    uint2 hv, lv;
    split4(acc, hv, lv);
    size_t eo = (size_t)warp * D + lane * 4;
    if (mode == 0) {
        *(float4*)(g_P1f + eo) = acc;
        *(uint2*)(g_P1h + eo) = hv;
        *(uint2*)(g_P1l + eo) = lv;
    } else {
        *(uint2*)(g_P2h + eo) = hv;
        *(uint2*)(g_P2l + eo) = lv;
    }
}

// ======================= mma.sync bf16 GEMM (3-term split) =======================
// Y = relu(X0*W0' + P1*W1' + P2*W2' + b); all operands pre-split bf16 hi/lo.
// 8 warps, warp tile 64x32, m16n8k16. 6 chunks of K=64, double-buffered cp.async.

#define ROW_W     36
#define BUF_W     (128 * ROW_W)
#define BUF_BYTES (BUF_W * 4)             // 18432
#define CH_BYTES  (4 * BUF_BYTES)         // 73728 (Ah,Al,Bh,Bl)
#define GSMEM     (2 * CH_BYTES)          // 147456 dynamic smem

__device__ __forceinline__ void mma_bf16(float* acc,
                                         uint32_t a0, uint32_t a1, uint32_t a2, uint32_t a3,
                                         uint32_t b0, uint32_t b1) {
    asm volatile(
        "mma.sync.aligned.m16n8k16.row.col.f32.bf16.bf16.f32 "
        "{%0,%1,%2,%3}, {%4,%5,%6,%7}, {%8,%9}, {%0,%1,%2,%3};"
        : "+f"(acc[0]), "+f"(acc[1]), "+f"(acc[2]), "+f"(acc[3])
        : "r"(a0), "r"(a1), "r"(a2), "r"(a3), "r"(b0), "r"(b1));
}

__device__ __forceinline__ void issue_chunk(
    uint32_t bb,
    const __nv_bfloat16* __restrict__ Xh, const __nv_bfloat16* __restrict__ Xl,
    const __nv_bfloat16* __restrict__ WH, const __nv_bfloat16* __restrict__ WL,
    int row0, int kk, int kbase, int tid)
{
#pragma unroll
    for (int i = 0; i < 4; ++i) {
        int idx = tid + i * 256;
        int r = idx >> 3, f = idx & 7;
        int grow = row0 + r; if (grow >= NN) grow = NN - 1;
        CP16(bb + (uint32_t)(r * ROW_W + f * 4) * 4,
             Xh + (size_t)grow * D + kk + f * 8);
    }
#pragma unroll
    for (int i = 0; i < 4; ++i) {
        int idx = tid + i * 256;
        int r = idx >> 3, f = idx & 7;
        int grow = row0 + r; if (grow >= NN) grow = NN - 1;
        CP16(bb + BUF_BYTES + (uint32_t)(r * ROW_W + f * 4) * 4,
             Xl + (size_t)grow * D + kk + f * 8);
    }
#pragma unroll
    for (int i = 0; i < 4; ++i) {
        int idx = tid + i * 256;
        int n = idx >> 3, f = idx & 7;
        CP16(bb + 2 * BUF_BYTES + (uint32_t)(n * ROW_W + f * 4) * 4,
             WH + (size_t)n * 384 + kbase + f * 8);
    }
#pragma unroll
    for (int i = 0; i < 4; ++i) {
        int idx = tid + i * 256;
        int n = idx >> 3, f = idx & 7;
        CP16(bb + 3 * BUF_BYTES + (uint32_t)(n * ROW_W + f * 4) * 4,
             WL + (size_t)n * 384 + kbase + f * 8);
    }
}

__global__ __launch_bounds__(256, 1)
void gemm_mma_kernel(int layer, const float* __restrict__ bias, int flip) {
    extern __shared__ uint32_t dsm[];
    uint32_t sbase = (uint32_t)__cvta_generic_to_shared(dsm);

    const __nv_bfloat16* AH0 = g_Fh[flip];
    const __nv_bfloat16* AL0 = g_Fl[flip];
    float*         Yf = (layer == 2) ? g_Ff[0] : g_Ff[flip ^ 1];  // layer2: pred reads Ff[0]? no — see below
    __nv_bfloat16* Yh = g_Fh[flip ^ 1];
    __nv_bfloat16* Yl = g_Fl[flip ^ 1];
    const __nv_bfloat16* WH = g_Whi + (size_t)layer * 128 * 384;
    const __nv_bfloat16* WL = g_Wlo + (size_t)layer * 128 * 384;
    bool last = (layer == 2);
    Yf = g_Ff[flip ^ 1];                   // fp32 always goes to the ping-pong slot

    int tid = threadIdx.x;
    int wid = tid >> 5;
    int lane = tid & 31;
    int g   = lane >> 2;
    int tig = lane & 3;
    int row0 = blockIdx.x * 128;

    int m0w = (wid >> 2) * 64;
    int n0w = (wid & 3) * 32;

    float acc[4][4][4];
#pragma unroll
    for (int mi = 0; mi < 4; ++mi)
#pragma unroll
        for (int ni = 0; ni < 4; ++ni)
#pragma unroll
            for (int q = 0; q < 4; ++q) acc[mi][ni][q] = 0.f;

    issue_chunk(sbase, AH0, AL0, WH, WL, row0, 0, 0, tid);
    CP_COMMIT();

    for (int c = 0; c < 6; ++c) {
        if (c < 5) {
            int nc = c + 1;
            int srcI = nc >> 1, kk = (nc & 1) * 64;
            const __nv_bfloat16* Xh = (srcI == 0) ? AH0 : ((srcI == 1) ? g_P1h : g_P2h);
            const __nv_bfloat16* Xl = (srcI == 0) ? AL0 : ((srcI == 1) ? g_P1l : g_P2l);
            issue_chunk(sbase + (uint32_t)(nc & 1) * CH_BYTES,
                        Xh, Xl, WH, WL, row0, kk, srcI * 128 + kk, tid);
            CP_COMMIT();
            CP_WAIT(1);
        } else {
            CP_WAIT(0);
        }
        __syncthreads();

        const uint32_t* Ah = dsm + (size_t)(c & 1) * (4 * BUF_W);
        const uint32_t* Al = Ah + BUF_W;
        const uint32_t* Bh = Ah + 2 * BUF_W;
        const uint32_t* Bl = Ah + 3 * BUF_W;

#pragma unroll
        for (int ks = 0; ks < 4; ++ks) {
            int kw = ks * 8;
            uint32_t ah[4][4], al[4][4], bh[4][2], bl[4][2];
#pragma unroll
            for (int mi = 0; mi < 4; ++mi) {
                const uint32_t* ph = Ah + (m0w + mi * 16 + g) * ROW_W + kw + tig;
                const uint32_t* pl = Al + (m0w + mi * 16 + g) * ROW_W + kw + tig;
                ah[mi][0] = ph[0];             al[mi][0] = pl[0];
                ah[mi][1] = ph[8 * ROW_W];     al[mi][1] = pl[8 * ROW_W];
                ah[mi][2] = ph[4];             al[mi][2] = pl[4];
                ah[mi][3] = ph[8 * ROW_W + 4]; al[mi][3] = pl[8 * ROW_W + 4];
            }
#pragma unroll
            for (int ni = 0; ni < 4; ++ni) {
                const uint32_t* ph = Bh + (n0w + ni * 8 + g) * ROW_W + kw + tig;
                const uint32_t* pl = Bl + (n0w + ni * 8 + g) * ROW_W + kw + tig;
                bh[ni][0] = ph[0]; bh[ni][1] = ph[4];
                bl[ni][0] = pl[0]; bl[ni][1] = pl[4];
            }
#pragma unroll
            for (int mi = 0; mi < 4; ++mi)
#pragma unroll
                for (int ni = 0; ni < 4; ++ni) {
                    mma_bf16(acc[mi][ni], ah[mi][0], ah[mi][1], ah[mi][2], ah[mi][3],
                             bh[ni][0], bh[ni][1]);
                    mma_bf16(acc[mi][ni], ah[mi][0], ah[mi][1], ah[mi][2], ah[mi][3],
                             bl[ni][0], bl[ni][1]);
                    mma_bf16(acc[mi][ni], al[mi][0], al[mi][1], al[mi][2], al[mi][3],
                             bh[ni][0], bh[ni][1]);
                }
        }
        __syncthreads();
    }

    // ---- epilogue: + bias, relu; fp32 always; hi/lo only when next GEMM needs it
#pragma unroll
    for (int mi = 0; mi < 4; ++mi) {
        int r0 = row0 + m0w + mi * 16 + g;
        int r1 = r0 + 8;
#pragma unroll
        for (int ni = 0; ni < 4; ++ni) {
            int c = n0w + ni * 8 + 2 * tig;
            float2 bb = *(const float2*)(bias + c);
            if (r0 < NN) {
                float vx = fmaxf(acc[mi][ni][0] + bb.x, 0.f);
                float vy = fmaxf(acc[mi][ni][1] + bb.y, 0.f);
                *(float2*)(Yf + (size_t)r0 * D + c) = make_float2(vx, vy);
                if (!last) {
                    __nv_bfloat16 h0 = __float2bfloat16_rn(vx);
                    __nv_bfloat16 h1 = __float2bfloat16_rn(vy);
                    *(uint32_t*)(Yh + (size_t)r0 * D + c) =
                        pack2(__bfloat162float(h0), __bfloat162float(h1));
                    *(uint32_t*)(Yl + (size_t)r0 * D + c) =
                        pack2(vx - __bfloat162float(h0), vy - __bfloat162float(h1));
                }
            }
            if (r1 < NN) {
                float vx = fmaxf(acc[mi][ni][2] + bb.x, 0.f);
                float vy = fmaxf(acc[mi][ni][3] + bb.y, 0.f);
                *(float2*)(Yf + (size_t)r1 * D + c) = make_float2(vx, vy);
                if (!last) {
                    __nv_bfloat16 h0 = __float2bfloat16_rn(vx);
                    __nv_bfloat16 h1 = __float2bfloat16_rn(vy);
                    *(uint32_t*)(Yh + (size_t)r1 * D + c) =
                        pack2(__bfloat162float(h0), __bfloat162float(h1));
                    *(uint32_t*)(Yl + (size_t)r1 * D + c) =
                        pack2(vx - __bfloat162float(h0), vy - __bfloat162float(h1));
                }
            }
        }
    }
}

// ---------------- prediction head ----------------
__global__ void pred_kernel(const float* __restrict__ pw,
                            const float* __restrict__ pb,
                            float* __restrict__ out) {
    int warp = (blockIdx.x * blockDim.x + threadIdx.x) >> 5;
    if (warp >= NN) return;
    int lane = threadIdx.x & 31;
    float4 e = ((const float4*)(g_Ff[1] + (size_t)warp * D))[lane];
    float4 p = __ldg((const float4*)pw + lane);
    float s = e.x * p.x + e.y * p.y + e.z * p.z + e.w * p.w;
#pragma unroll
    for (int o = 16; o; o >>= 1) s += __shfl_xor_sync(0xffffffffu, s, o);
    if (lane == 0) out[warp] = s + __ldg(pb);
}

// ---------------- host launch ----------------
extern "C" void kernel_launch(void* const* d_in, const int* in_sizes, int n_in,
                              void* d_out, int out_size) {
    const float* weights = (const float*)d_in[0];
    const int*   src     = (const int*)d_in[1];
    const int*   dst     = (const int*)d_in[2];
    const float* lin_w   = (const float*)d_in[3];
    const float* lin_b   = (const float*)d_in[4];
    const float* cheb_ws = (const float*)d_in[5];
    const float* cheb_bs = (const float*)d_in[6];
    const float* pred_w  = (const float*)d_in[7];
    const float* pred_b  = (const float*)d_in[8];
    float* out = (float*)d_out;

    cudaFuncSetAttribute(gemm_mma_kernel,
                         cudaFuncAttributeMaxDynamicSharedMemorySize, GSMEM);
    cudaFuncSetAttribute(scan_kernel,
                         cudaFuncAttributeMaxDynamicSharedMemorySize, NN * 4);

    // fused count | feat | wprep, then scan, then scatter
    prep_kernel   <<<NB_PREP, 256>>>(dst, weights, lin_w, lin_b, cheb_ws);
    scan_kernel   <<<1, 1024, NN * 4>>>();
    scatter_kernel<<<(NT + 255) / 256, 256>>>(src, dst);

    const int spmm_blocks = (NN * 32 + 255) / 256;   // one warp per node
    const int gemm_blocks = (NN + 127) / 128;        // 391

    for (int l = 0; l < 3; ++l) {
        int flip = l & 1;
        spmm_kernel<<<spmm_blocks, 256>>>(0, flip);   // P1 = A~ X0
        spmm_kernel<<<spmm_blocks, 256>>>(1, flip);   // P2 = A~ P1
        gemm_mma_kernel<<<gemm_blocks, 256, GSMEM>>>(
            l, cheb_bs + (size_t)l * 128, flip);
        // inter-layer leaky_relu(relu(x)) == relu(x): no-op, skipped
    }

    pred_kernel<<<spmm_blocks, 256>>>(pred_w, pred_b, out);
}

// round 12
// speedup vs baseline: 1.0802x; 1.0171x over previous
#include <cuda_runtime.h>
#include <cuda_bf16.h>
#include <cstdint>

#define NN   50000
#define NE   600000
#define NT   (NE + NN)     // edges + self loops = 650000
#define D    128

// ---------------- device scratch (static, no runtime alloc) ----------------
__device__ float         g_Ff[2][(size_t)NN * D];
__device__ __nv_bfloat16 g_Fh[2][(size_t)NN * D];
__device__ __nv_bfloat16 g_Fl[2][(size_t)NN * D];
__device__ float         g_P1f[(size_t)NN * D];
__device__ __nv_bfloat16 g_P1h[(size_t)NN * D];
__device__ __nv_bfloat16 g_P1l[(size_t)NN * D];
__device__ __nv_bfloat16 g_P2h[(size_t)NN * D];
__device__ __nv_bfloat16 g_P2l[(size_t)NN * D];
__device__ int2  g_colew[NT];            // packed {col*D, bitcast(weight)}
__device__ int   g_rowptr[NN + 1];
__device__ int   g_deg[NN];              // zero-init at load; scan self-resets
__device__ int   g_epos[NE];             // per-edge slot within its row
__device__ float g_dinv[NN];
// Folded W (W0-W2, -W1, 2*W2) as bf16 hi/lo, transposed: [layer][n(128)][k(384)]
__device__ __nv_bfloat16 g_Whi[3 * 128 * 384];
__device__ __nv_bfloat16 g_Wlo[3 * 128 * 384];

// ---------------- helpers ----------------
__device__ __forceinline__ uint32_t pack2(float a, float b) {
    __nv_bfloat162 h = __floats2bfloat162_rn(a, b);
    return *reinterpret_cast<uint32_t*>(&h);
}
__device__ __forceinline__ void split4(float4 v, uint2& hv, uint2& lv) {
    __nv_bfloat16 h0 = __float2bfloat16_rn(v.x);
    __nv_bfloat16 h1 = __float2bfloat16_rn(v.y);
    __nv_bfloat16 h2 = __float2bfloat16_rn(v.z);
    __nv_bfloat16 h3 = __float2bfloat16_rn(v.w);
    hv = make_uint2(pack2(__bfloat162float(h0), __bfloat162float(h1)),
                    pack2(__bfloat162float(h2), __bfloat162float(h3)));
    lv = make_uint2(pack2(v.x - __bfloat162float(h0), v.y - __bfloat162float(h1)),
                    pack2(v.z - __bfloat162float(h2), v.w - __bfloat162float(h3)));
}

#define CP16(daddr, gptr) \
    asm volatile("cp.async.cg.shared.global [%0], [%1], 16;" \
        :: "r"(daddr), "l"(gptr))
#define CP_COMMIT() asm volatile("cp.async.commit_group;" ::: "memory")
#define CP_WAIT(n)  asm volatile("cp.async.wait_group %0;" :: "n"(n) : "memory")

// ---------------- fused prep: count degrees (+slot) | input linear | W fold ----
#define NB_COUNT ((NE + 255) / 256)               // 2344
#define NB_FEAT  ((NN * (D / 4) + 255) / 256)     // 6250
#define NB_WPREP ((3 * 384 * 128 + 255) / 256)    // 576
#define NB_PREP  (NB_COUNT + NB_FEAT + NB_WPREP)

__global__ void prep_kernel(const int* __restrict__ dst,
                            const float* __restrict__ w,
                            const float* __restrict__ lw,
                            const float* __restrict__ lb,
                            const float* __restrict__ cheb_ws) {
    int b = blockIdx.x;
    int tid = threadIdx.x;
    if (b < NB_COUNT) {
        int e = b * 256 + tid;
        if (e < NE) g_epos[e] = atomicAdd(&g_deg[dst[e]], 1);
    } else if (b < NB_COUNT + NB_FEAT) {
        int i = (b - NB_COUNT) * 256 + tid;
        if (i >= NN * (D / 4)) return;
        int v  = i >> 5;
        int d4 = i & 31;
        float s = __ldg(w + v);
        float4 a = __ldg((const float4*)lw + d4);
        float4 bb = __ldg((const float4*)lb + d4);
        float4 r;
        r.x = fmaf(s, a.x, bb.x); r.y = fmaf(s, a.y, bb.y);
        r.z = fmaf(s, a.z, bb.z); r.w = fmaf(s, a.w, bb.w);
        ((float4*)g_Ff[0])[i] = r;
        uint2 hv, lv;
        split4(r, hv, lv);
        *(uint2*)(g_Fh[0] + (size_t)i * 4) = hv;
        *(uint2*)(g_Fl[0] + (size_t)i * 4) = lv;
    } else {
        int i = (b - NB_COUNT - NB_FEAT) * 256 + tid;
        if (i >= 3 * 384 * 128) return;
        int l   = i / (384 * 128);
        int rem = i % (384 * 128);
        int k = rem >> 7;
        int n = rem & 127;
        int seg = k >> 7;
        int kin = k & 127;
        const float* WL0 = cheb_ws + (size_t)l * 384 * 128;
        float wv;
        if (seg == 0)      wv = __ldg(WL0 + (size_t)k * 128 + n) - __ldg(WL0 + (size_t)(256 + kin) * 128 + n);
        else if (seg == 1) wv = -__ldg(WL0 + (size_t)k * 128 + n);
        else               wv = 2.0f * __ldg(WL0 + (size_t)k * 128 + n);
        __nv_bfloat16 h = __float2bfloat16_rn(wv);
        size_t o = ((size_t)l * 128 + n) * 384 + k;
        g_Whi[o] = h;
        g_Wlo[o] = __float2bfloat16_rn(wv - __bfloat162float(h));
    }
}

// ---------------- CSR: single-block scan (smem-staged, self-resetting) --------
__global__ void scan_kernel() {
    extern __shared__ int ssm[];            // NN ints
    __shared__ int part[1024];
    const int T = 1024;
    const int CHUNK = (NN + T - 1) / T;     // 49
    int tid = threadIdx.x;

    for (int i = tid; i < NN; i += T) {
        ssm[i] = g_deg[i] + 1;              // +1 self loop
        g_deg[i] = 0;
    }
    __syncthreads();

    int start = tid * CHUNK;
    int end = start + CHUNK; if (end > NN) end = NN;
    int s = 0;
    for (int i = start; i < end; ++i) s += ssm[i];
    part[tid] = s;
    __syncthreads();
    for (int off = 1; off < T; off <<= 1) {
        int v = (tid >= off) ? part[tid - off] : 0;
        __syncthreads();
        part[tid] += v;
        __syncthreads();
    }
    int run = part[tid] - s;
    for (int i = start; i < end; ++i) {
        int v = ssm[i];
        ssm[i] = run;
        run += v;
    }
    __syncthreads();
    int total = part[T - 1];
    for (int i = tid; i < NN; i += T) {
        int rp = ssm[i];
        g_rowptr[i] = rp;
        int nxt = (i + 1 < NN) ? ssm[i + 1] : total;
        g_dinv[i] = rsqrtf((float)(nxt - rp));
    }
    if (tid == 0) g_rowptr[NN] = total;
}

__global__ void scatter_kernel(const int* __restrict__ src, const int* __restrict__ dst) {
    int e = blockIdx.x * blockDim.x + threadIdx.x;
    if (e >= NT) return;
    int s, d, pos;
    if (e < NE) {
        s = src[e]; d = dst[e];
        pos = g_rowptr[d] + g_epos[e];
    } else {
        s = d = e - NE;
        pos = g_rowptr[d + 1] - 1;           // self loop takes the last slot
    }
    g_colew[pos] = make_int2(s * D, __float_as_int(g_dinv[s] * g_dinv[d]));
}

// ---------------- SpMM: out = A_norm @ X (fp32 gather, high occupancy) ---------
__global__ __launch_bounds__(256, 7)
void spmm_kernel(int mode, int flip) {
    const float* __restrict__ X = (mode == 0) ? g_Ff[flip] : g_P1f;

    int warp = (blockIdx.x * blockDim.x + threadIdx.x) >> 5;
    if (warp >= NN) return;
    int lane = threadIdx.x & 31;
    int beg = g_rowptr[warp];
    int end = g_rowptr[warp + 1];

    const float* Xl4 = X + lane * 4;       // lane-fixed base; edge offset pre-scaled

    float4 acc = make_float4(0.f, 0.f, 0.f, 0.f);
    int p = beg;
    for (; p + 3 < end; p += 4) {
        int2 e0 = __ldg(g_colew + p);
        int2 e1 = __ldg(g_colew + p + 1);
        int2 e2 = __ldg(g_colew + p + 2);
        int2 e3 = __ldg(g_colew + p + 3);
        float4 x0 = *(const float4*)(Xl4 + e0.x);
        float4 x1 = *(const float4*)(Xl4 + e1.x);
        float4 x2 = *(const float4*)(Xl4 + e2.x);
        float4 x3 = *(const float4*)(Xl4 + e3.x);
        float w0 = __int_as_float(e0.y);
        float w1 = __int_as_float(e1.y);
        float w2 = __int_as_float(e2.y);
        float w3 = __int_as_float(e3.y);
        acc.x = fmaf(w0, x0.x, acc.x); acc.y = fmaf(w0, x0.y, acc.y);
        acc.z = fmaf(w0, x0.z, acc.z); acc.w = fmaf(w0, x0.w, acc.w);
        acc.x = fmaf(w1, x1.x, acc.x); acc.y = fmaf(w1, x1.y, acc.y);
        acc.z = fmaf(w1, x1.z, acc.z); acc.w = fmaf(w1, x1.w, acc.w);
        acc.x = fmaf(w2, x2.x, acc.x); acc.y = fmaf(w2, x2.y, acc.y);
        acc.z = fmaf(w2, x2.z, acc.z); acc.w = fmaf(w2, x2.w, acc.w);
        acc.x = fmaf(w3, x3.x, acc.x); acc.y = fmaf(w3, x3.y, acc.y);
        acc.z = fmaf(w3, x3.z, acc.z); acc.w = fmaf(w3, x3.w, acc.w);
    }
    for (; p < end; ++p) {
        int2 e0 = __ldg(g_colew + p);
        float w0 = __int_as_float(e0.y);
        float4 x0 = *(const float4*)(Xl4 + e0.x);
        acc.x = fmaf(w0, x0.x, acc.x); acc.y = fmaf(w0, x0.y, acc.y);
        acc.z = fmaf(w0, x0.z, acc.z); acc.w = fmaf(w0, x0.w, acc.w);
    }

    uint2 hv, lv;
    split4(acc, hv, lv);
    size_t eo = (size_t)warp * D + lane * 4;
    if (mode == 0) {
        *(float4*)(g_P1f + eo) = acc;
        *(uint2*)(g_P1h + eo) = hv;
        *(uint2*)(g_P1l + eo) = lv;
    } else {
        *(uint2*)(g_P2h + eo) = hv;
        *(uint2*)(g_P2l + eo) = lv;
    }
}

// ======================= mma.sync bf16 GEMM (3-term split) =======================
// Y = relu(X0*W0' + P1*W1' + P2*W2' + b); all operands pre-split bf16 hi/lo.
// 8 warps, warp tile 64x32, m16n8k16. 6 chunks of K=64, double-buffered cp.async.
// Layers 0,1: emit fp32 + bf16 hi/lo. Layer 2: fused pred head -> logits only.

#define ROW_W     36
#define BUF_W     (128 * ROW_W)
#define BUF_BYTES (BUF_W * 4)             // 18432
#define CH_BYTES  (4 * BUF_BYTES)         // 73728 (Ah,Al,Bh,Bl)
#define GSMEM     (2 * CH_BYTES)          // 147456 dynamic smem

__device__ __forceinline__ void mma_bf16(float* acc,
                                         uint32_t a0, uint32_t a1, uint32_t a2, uint32_t a3,
                                         uint32_t b0, uint32_t b1) {
    asm volatile(
        "mma.sync.aligned.m16n8k16.row.col.f32.bf16.bf16.f32 "
        "{%0,%1,%2,%3}, {%4,%5,%6,%7}, {%8,%9}, {%0,%1,%2,%3};"
        : "+f"(acc[0]), "+f"(acc[1]), "+f"(acc[2]), "+f"(acc[3])
        : "r"(a0), "r"(a1), "r"(a2), "r"(a3), "r"(b0), "r"(b1));
}

__device__ __forceinline__ void issue_chunk(
    uint32_t bb,
    const __nv_bfloat16* __restrict__ Xh, const __nv_bfloat16* __restrict__ Xl,
    const __nv_bfloat16* __restrict__ WH, const __nv_bfloat16* __restrict__ WL,
    int row0, int kk, int kbase, int tid)
{
#pragma unroll
    for (int i = 0; i < 4; ++i) {
        int idx = tid + i * 256;
        int r = idx >> 3, f = idx & 7;
        int grow = row0 + r; if (grow >= NN) grow = NN - 1;
        CP16(bb + (uint32_t)(r * ROW_W + f * 4) * 4,
             Xh + (size_t)grow * D + kk + f * 8);
    }
#pragma unroll
    for (int i = 0; i < 4; ++i) {
        int idx = tid + i * 256;
        int r = idx >> 3, f = idx & 7;
        int grow = row0 + r; if (grow >= NN) grow = NN - 1;
        CP16(bb + BUF_BYTES + (uint32_t)(r * ROW_W + f * 4) * 4,
             Xl + (size_t)grow * D + kk + f * 8);
    }
#pragma unroll
    for (int i = 0; i < 4; ++i) {
        int idx = tid + i * 256;
        int n = idx >> 3, f = idx & 7;
        CP16(bb + 2 * BUF_BYTES + (uint32_t)(n * ROW_W + f * 4) * 4,
             WH + (size_t)n * 384 + kbase + f * 8);
    }
#pragma unroll
    for (int i = 0; i < 4; ++i) {
        int idx = tid + i * 256;
        int n = idx >> 3, f = idx & 7;
        CP16(bb + 3 * BUF_BYTES + (uint32_t)(n * ROW_W + f * 4) * 4,
             WL + (size_t)n * 384 + kbase + f * 8);
    }
}

__global__ __launch_bounds__(256, 1)
void gemm_mma_kernel(int layer, const float* __restrict__ bias, int flip,
                     const float* __restrict__ pw, const float* __restrict__ pb,
                     float* __restrict__ out) {
    extern __shared__ uint32_t dsm[];
    uint32_t sbase = (uint32_t)__cvta_generic_to_shared(dsm);

    const __nv_bfloat16* AH0 = g_Fh[flip];
    const __nv_bfloat16* AL0 = g_Fl[flip];
    float*         Yf = g_Ff[flip ^ 1];
    __nv_bfloat16* Yh = g_Fh[flip ^ 1];
    __nv_bfloat16* Yl = g_Fl[flip ^ 1];
    const __nv_bfloat16* WH = g_Whi + (size_t)layer * 128 * 384;
    const __nv_bfloat16* WL = g_Wlo + (size_t)layer * 128 * 384;
    bool last = (layer == 2);

    int tid = threadIdx.x;
    int wid = tid >> 5;
    int lane = tid & 31;
    int g   = lane >> 2;
    int tig = lane & 3;
    int row0 = blockIdx.x * 128;

    int m0w = (wid >> 2) * 64;
    int n0w = (wid & 3) * 32;

    float acc[4][4][4];
#pragma unroll
    for (int mi = 0; mi < 4; ++mi)
#pragma unroll
        for (int ni = 0; ni < 4; ++ni)
#pragma unroll
            for (int q = 0; q < 4; ++q) acc[mi][ni][q] = 0.f;

    issue_chunk(sbase, AH0, AL0, WH, WL, row0, 0, 0, tid);
    CP_COMMIT();

    for (int c = 0; c < 6; ++c) {
        if (c < 5) {
            int nc = c + 1;
            int srcI = nc >> 1, kk = (nc & 1) * 64;
            const __nv_bfloat16* Xh = (srcI == 0) ? AH0 : ((srcI == 1) ? g_P1h : g_P2h);
            const __nv_bfloat16* Xl = (srcI == 0) ? AL0 : ((srcI == 1) ? g_P1l : g_P2l);
            issue_chunk(sbase + (uint32_t)(nc & 1) * CH_BYTES,
                        Xh, Xl, WH, WL, row0, kk, srcI * 128 + kk, tid);
            CP_COMMIT();
            CP_WAIT(1);
        } else {
            CP_WAIT(0);
        }
        __syncthreads();

        const uint32_t* Ah = dsm + (size_t)(c & 1) * (4 * BUF_W);
        const uint32_t* Al = Ah + BUF_W;
        const uint32_t* Bh = Ah + 2 * BUF_W;
        const uint32_t* Bl = Ah + 3 * BUF_W;

#pragma unroll
        for (int ks = 0; ks < 4; ++ks) {
            int kw = ks * 8;
            uint32_t ah[4][4], al[4][4], bh[4][2], bl[4][2];
#pragma unroll
            for (int mi = 0; mi < 4; ++mi) {
                const uint32_t* ph = Ah + (m0w + mi * 16 + g) * ROW_W + kw + tig;
                const uint32_t* pl = Al + (m0w + mi * 16 + g) * ROW_W + kw + tig;
                ah[mi][0] = ph[0];             al[mi][0] = pl[0];
                ah[mi][1] = ph[8 * ROW_W];     al[mi][1] = pl[8 * ROW_W];
                ah[mi][2] = ph[4];             al[mi][2] = pl[4];
                ah[mi][3] = ph[8 * ROW_W + 4]; al[mi][3] = pl[8 * ROW_W + 4];
            }
#pragma unroll
            for (int ni = 0; ni < 4; ++ni) {
                const uint32_t* ph = Bh + (n0w + ni * 8 + g) * ROW_W + kw + tig;
                const uint32_t* pl = Bl + (n0w + ni * 8 + g) * ROW_W + kw + tig;
                bh[ni][0] = ph[0]; bh[ni][1] = ph[4];
                bl[ni][0] = pl[0]; bl[ni][1] = pl[4];
            }
#pragma unroll
            for (int mi = 0; mi < 4; ++mi)
#pragma unroll
                for (int ni = 0; ni < 4; ++ni) {
                    mma_bf16(acc[mi][ni], ah[mi][0], ah[mi][1], ah[mi][2], ah[mi][3],
                             bh[ni][0], bh[ni][1]);
                    mma_bf16(acc[mi][ni], ah[mi][0], ah[mi][1], ah[mi][2], ah[mi][3],
                             bl[ni][0], bl[ni][1]);
                    mma_bf16(acc[mi][ni], al[mi][0], al[mi][1], al[mi][2], al[mi][3],
                             bh[ni][0], bh[ni][1]);
                }
        }
        __syncthreads();
    }

    if (!last) {
        // ---- epilogue: + bias, relu -> fp32 + bf16 hi/lo ----
#pragma unroll
        for (int mi = 0; mi < 4; ++mi) {
            int r0 = row0 + m0w + mi * 16 + g;
            int r1 = r0 + 8;
#pragma unroll
            for (int ni = 0; ni < 4; ++ni) {
                int c = n0w + ni * 8 + 2 * tig;
                float2 bb = *(const float2*)(bias + c);
                if (r0 < NN) {
                    float vx = fmaxf(acc[mi][ni][0] + bb.x, 0.f);
                    float vy = fmaxf(acc[mi][ni][1] + bb.y, 0.f);
                    *(float2*)(Yf + (size_t)r0 * D + c) = make_float2(vx, vy);
                    __nv_bfloat16 h0 = __float2bfloat16_rn(vx);
                    __nv_bfloat16 h1 = __float2bfloat16_rn(vy);
                    *(uint32_t*)(Yh + (size_t)r0 * D + c) =
                        pack2(__bfloat162float(h0), __bfloat162float(h1));
                    *(uint32_t*)(Yl + (size_t)r0 * D + c) =
                        pack2(vx - __bfloat162float(h0), vy - __bfloat162float(h1));
                }
                if (r1 < NN) {
                    float vx = fmaxf(acc[mi][ni][2] + bb.x, 0.f);
                    float vy = fmaxf(acc[mi][ni][3] + bb.y, 0.f);
                    *(float2*)(Yf + (size_t)r1 * D + c) = make_float2(vx, vy);
                    __nv_bfloat16 h0 = __float2bfloat16_rn(vx);
                    __nv_bfloat16 h1 = __float2bfloat16_rn(vy);
                    *(uint32_t*)(Yh + (size_t)r1 * D + c) =
                        pack2(__bfloat162float(h0), __bfloat162float(h1));
                    *(uint32_t*)(Yl + (size_t)r1 * D + c) =
                        pack2(vx - __bfloat162float(h0), vy - __bfloat162float(h1));
                }
            }
        }
    } else {
        // ---- fused prediction head: out[r] = relu(acc + b) . pw + pb ----
        float* red = (float*)dsm;          // 128 floats, smem now free
        if (tid < 128) red[tid] = 0.f;
        __syncthreads();
#pragma unroll
        for (int mi = 0; mi < 4; ++mi) {
            float p0 = 0.f, p1 = 0.f;
#pragma unroll
            for (int ni = 0; ni < 4; ++ni) {
                int c = n0w + ni * 8 + 2 * tig;
                float2 bb = *(const float2*)(bias + c);
                float2 pp = __ldg((const float2*)(pw + c));
                float vx = fmaxf(acc[mi][ni][0] + bb.x, 0.f);
                float vy = fmaxf(acc[mi][ni][1] + bb.y, 0.f);
                p0 += vx * pp.x + vy * pp.y;
                vx = fmaxf(acc[mi][ni][2] + bb.x, 0.f);
                vy = fmaxf(acc[mi][ni][3] + bb.y, 0.f);
                p1 += vx * pp.x + vy * pp.y;
            }
            atomicAdd(&red[m0w + mi * 16 + g], p0);
            atomicAdd(&red[m0w + mi * 16 + 8 + g], p1);
        }
        __syncthreads();
        if (tid < 128) {
            int r = row0 + tid;
            if (r < NN) out[r] = red[tid] + __ldg(pb);
        }
    }
}

// ---------------- host launch ----------------
extern "C" void kernel_launch(void* const* d_in, const int* in_sizes, int n_in,
                              void* d_out, int out_size) {
    const float* weights = (const float*)d_in[0];
    const int*   src     = (const int*)d_in[1];
    const int*   dst     = (const int*)d_in[2];
    const float* lin_w   = (const float*)d_in[3];
    const float* lin_b   = (const float*)d_in[4];
    const float* cheb_ws = (const float*)d_in[5];
    const float* cheb_bs = (const float*)d_in[6];
    const float* pred_w  = (const float*)d_in[7];
    const float* pred_b  = (const float*)d_in[8];
    float* out = (float*)d_out;

    cudaFuncSetAttribute(gemm_mma_kernel,
                         cudaFuncAttributeMaxDynamicSharedMemorySize, GSMEM);
    cudaFuncSetAttribute(scan_kernel,
                         cudaFuncAttributeMaxDynamicSharedMemorySize, NN * 4);

    // fused count | feat | wprep, then scan, then scatter
    prep_kernel   <<<NB_PREP, 256>>>(dst, weights, lin_w, lin_b, cheb_ws);
    scan_kernel   <<<1, 1024, NN * 4>>>();
    scatter_kernel<<<(NT + 255) / 256, 256>>>(src, dst);

    const int spmm_blocks = (NN * 32 + 255) / 256;   // one warp per node
    const int gemm_blocks = (NN + 127) / 128;        // 391

    for (int l = 0; l < 3; ++l) {
        int flip = l & 1;
        spmm_kernel<<<spmm_blocks, 256>>>(0, flip);   // P1 = A~ X0
        spmm_kernel<<<spmm_blocks, 256>>>(1, flip);   // P2 = A~ P1
        gemm_mma_kernel<<<gemm_blocks, 256, GSMEM>>>(
            l, cheb_bs + (size_t)l * 128, flip, pred_w, pred_b, out);
        // inter-layer leaky_relu(relu(x)) == relu(x): no-op, skipped
    }
}

// round 13
// speedup vs baseline: 1.2096x; 1.1198x over previous
#include <cuda_runtime.h>
#include <cuda_bf16.h>
#include <cuda_fp16.h>
#include <cstdint>

#define NN   50000
#define NE   600000
#define NT   (NE + NN)     // edges + self loops = 650000
#define D    128

// ---------------- device scratch (static, no runtime alloc) ----------------
// Features: fp16 (SpMM gather path) + bf16 hi/lo pair (GEMM path, 2^-17).
__device__ __half        g_X16[2][(size_t)NN * D];
__device__ __nv_bfloat16 g_Fh[2][(size_t)NN * D];
__device__ __nv_bfloat16 g_Fl[2][(size_t)NN * D];
__device__ __half        g_P116[(size_t)NN * D];
__device__ __nv_bfloat16 g_P1h[(size_t)NN * D];
__device__ __nv_bfloat16 g_P1l[(size_t)NN * D];
__device__ __nv_bfloat16 g_P2h[(size_t)NN * D];
__device__ __nv_bfloat16 g_P2l[(size_t)NN * D];
__device__ int2  g_colew[NT];            // packed {col*D, bitcast(weight)}
__device__ int   g_rowptr[NN + 1];
__device__ int   g_deg[NN];              // zero-init at load; scan self-resets
__device__ int   g_epos[NE];             // per-edge slot within its row
__device__ float g_dinv[NN];
// Folded W (W0-W2, -W1, 2*W2) as bf16 hi/lo, transposed: [layer][n(128)][k(384)]
__device__ __nv_bfloat16 g_Whi[3 * 128 * 384];
__device__ __nv_bfloat16 g_Wlo[3 * 128 * 384];

// ---------------- helpers ----------------
__device__ __forceinline__ uint32_t pack2(float a, float b) {
    __nv_bfloat162 h = __floats2bfloat162_rn(a, b);
    return *reinterpret_cast<uint32_t*>(&h);
}
__device__ __forceinline__ void split4(float4 v, uint2& hv, uint2& lv) {
    __nv_bfloat16 h0 = __float2bfloat16_rn(v.x);
    __nv_bfloat16 h1 = __float2bfloat16_rn(v.y);
    __nv_bfloat16 h2 = __float2bfloat16_rn(v.z);
    __nv_bfloat16 h3 = __float2bfloat16_rn(v.w);
    hv = make_uint2(pack2(__bfloat162float(h0), __bfloat162float(h1)),
                    pack2(__bfloat162float(h2), __bfloat162float(h3)));
    lv = make_uint2(pack2(v.x - __bfloat162float(h0), v.y - __bfloat162float(h1)),
                    pack2(v.z - __bfloat162float(h2), v.w - __bfloat162float(h3)));
}
__device__ __forceinline__ uint2 half4_of(float4 v) {
    __half2 q01 = __floats2half2_rn(v.x, v.y);
    __half2 q23 = __floats2half2_rn(v.z, v.w);
    return make_uint2(*reinterpret_cast<uint32_t*>(&q01),
                      *reinterpret_cast<uint32_t*>(&q23));
}

#define CP16(daddr, gptr) \
    asm volatile("cp.async.cg.shared.global [%0], [%1], 16;" \
        :: "r"(daddr), "l"(gptr))
#define CP_COMMIT() asm volatile("cp.async.commit_group;" ::: "memory")
#define CP_WAIT(n)  asm volatile("cp.async.wait_group %0;" :: "n"(n) : "memory")

// ---------------- fused prep: count degrees (+slot) | input linear | W fold ----
#define NB_COUNT ((NE + 255) / 256)               // 2344
#define NB_FEAT  ((NN * (D / 4) + 255) / 256)     // 6250
#define NB_WPREP ((3 * 384 * 128 + 255) / 256)    // 576
#define NB_PREP  (NB_COUNT + NB_FEAT + NB_WPREP)

__global__ void prep_kernel(const int* __restrict__ dst,
                            const float* __restrict__ w,
                            const float* __restrict__ lw,
                            const float* __restrict__ lb,
                            const float* __restrict__ cheb_ws) {
    int b = blockIdx.x;
    int tid = threadIdx.x;
    if (b < NB_COUNT) {
        int e = b * 256 + tid;
        if (e < NE) g_epos[e] = atomicAdd(&g_deg[dst[e]], 1);
    } else if (b < NB_COUNT + NB_FEAT) {
        int i = (b - NB_COUNT) * 256 + tid;
        if (i >= NN * (D / 4)) return;
        int v  = i >> 5;
        int d4 = i & 31;
        float s = __ldg(w + v);
        float4 a = __ldg((const float4*)lw + d4);
        float4 bb = __ldg((const float4*)lb + d4);
        float4 r;
        r.x = fmaf(s, a.x, bb.x); r.y = fmaf(s, a.y, bb.y);
        r.z = fmaf(s, a.z, bb.z); r.w = fmaf(s, a.w, bb.w);
        *(uint2*)(g_X16[0] + (size_t)i * 4) = half4_of(r);
        uint2 hv, lv;
        split4(r, hv, lv);
        *(uint2*)(g_Fh[0] + (size_t)i * 4) = hv;
        *(uint2*)(g_Fl[0] + (size_t)i * 4) = lv;
    } else {
        int i = (b - NB_COUNT - NB_FEAT) * 256 + tid;
        if (i >= 3 * 384 * 128) return;
        int l   = i / (384 * 128);
        int rem = i % (384 * 128);
        int k = rem >> 7;
        int n = rem & 127;
        int seg = k >> 7;
        int kin = k & 127;
        const float* WL0 = cheb_ws + (size_t)l * 384 * 128;
        float wv;
        if (seg == 0)      wv = __ldg(WL0 + (size_t)k * 128 + n) - __ldg(WL0 + (size_t)(256 + kin) * 128 + n);
        else if (seg == 1) wv = -__ldg(WL0 + (size_t)k * 128 + n);
        else               wv = 2.0f * __ldg(WL0 + (size_t)k * 128 + n);
        __nv_bfloat16 h = __float2bfloat16_rn(wv);
        size_t o = ((size_t)l * 128 + n) * 384 + k;
        g_Whi[o] = h;
        g_Wlo[o] = __float2bfloat16_rn(wv - __bfloat162float(h));
    }
}

// ---------------- CSR: single-block scan (smem-staged, self-resetting) --------
__global__ void scan_kernel() {
    extern __shared__ int ssm[];            // NN ints
    __shared__ int part[1024];
    const int T = 1024;
    const int CHUNK = (NN + T - 1) / T;     // 49
    int tid = threadIdx.x;

    for (int i = tid; i < NN; i += T) {
        ssm[i] = g_deg[i] + 1;              // +1 self loop
        g_deg[i] = 0;
    }
    __syncthreads();

    int start = tid * CHUNK;
    int end = start + CHUNK; if (end > NN) end = NN;
    int s = 0;
    for (int i = start; i < end; ++i) s += ssm[i];
    part[tid] = s;
    __syncthreads();
    for (int off = 1; off < T; off <<= 1) {
        int v = (tid >= off) ? part[tid - off] : 0;
        __syncthreads();
        part[tid] += v;
        __syncthreads();
    }
    int run = part[tid] - s;
    for (int i = start; i < end; ++i) {
        int v = ssm[i];
        ssm[i] = run;
        run += v;
    }
    __syncthreads();
    int total = part[T - 1];
    for (int i = tid; i < NN; i += T) {
        int rp = ssm[i];
        g_rowptr[i] = rp;
        int nxt = (i + 1 < NN) ? ssm[i + 1] : total;
        g_dinv[i] = rsqrtf((float)(nxt - rp));
    }
    if (tid == 0) g_rowptr[NN] = total;
}

__global__ void scatter_kernel(const int* __restrict__ src, const int* __restrict__ dst) {
    int e = blockIdx.x * blockDim.x + threadIdx.x;
    if (e >= NT) return;
    int s, d, pos;
    if (e < NE) {
        s = src[e]; d = dst[e];
        pos = g_rowptr[d] + g_epos[e];
    } else {
        s = d = e - NE;
        pos = g_rowptr[d + 1] - 1;           // self loop takes the last slot
    }
    g_colew[pos] = make_int2(s * D, __float_as_int(g_dinv[s] * g_dinv[d]));
}

// ---------------- SpMM: out = A_norm @ X (fp16 gather = half the L2 bytes) -----
__global__ __launch_bounds__(256, 7)
void spmm_kernel(int mode, int flip) {
    const __half* __restrict__ X = (mode == 0) ? g_X16[flip] : g_P116;

    int warp = (blockIdx.x * blockDim.x + threadIdx.x) >> 5;
    if (warp >= NN) return;
    int lane = threadIdx.x & 31;
    int beg = g_rowptr[warp];
    int end = g_rowptr[warp + 1];

    const __half* Xl4 = X + lane * 4;      // lane-fixed base; edge offset pre-scaled

    float4 acc = make_float4(0.f, 0.f, 0.f, 0.f);
    int p = beg;
    for (; p + 3 < end; p += 4) {
        int2 e0 = __ldg(g_colew + p);
        int2 e1 = __ldg(g_colew + p + 1);
        int2 e2 = __ldg(g_colew + p + 2);
        int2 e3 = __ldg(g_colew + p + 3);
        uint2 v0 = __ldg((const uint2*)(Xl4 + e0.x));
        uint2 v1 = __ldg((const uint2*)(Xl4 + e1.x));
        uint2 v2 = __ldg((const uint2*)(Xl4 + e2.x));
        uint2 v3 = __ldg((const uint2*)(Xl4 + e3.x));
        float w0 = __int_as_float(e0.y);
        float w1 = __int_as_float(e1.y);
        float w2 = __int_as_float(e2.y);
        float w3 = __int_as_float(e3.y);
        float2 a0 = __half22float2(*reinterpret_cast<__half2*>(&v0.x));
        float2 b0 = __half22float2(*reinterpret_cast<__half2*>(&v0.y));
        float2 a1 = __half22float2(*reinterpret_cast<__half2*>(&v1.x));
        float2 b1 = __half22float2(*reinterpret_cast<__half2*>(&v1.y));
        float2 a2 = __half22float2(*reinterpret_cast<__half2*>(&v2.x));
        float2 b2 = __half22float2(*reinterpret_cast<__half2*>(&v2.y));
        float2 a3 = __half22float2(*reinterpret_cast<__half2*>(&v3.x));
        float2 b3 = __half22float2(*reinterpret_cast<__half2*>(&v3.y));
        acc.x = fmaf(w0, a0.x, acc.x); acc.y = fmaf(w0, a0.y, acc.y);
        acc.z = fmaf(w0, b0.x, acc.z); acc.w = fmaf(w0, b0.y, acc.w);
        acc.x = fmaf(w1, a1.x, acc.x); acc.y = fmaf(w1, a1.y, acc.y);
        acc.z = fmaf(w1, b1.x, acc.z); acc.w = fmaf(w1, b1.y, acc.w);
        acc.x = fmaf(w2, a2.x, acc.x); acc.y = fmaf(w2, a2.y, acc.y);
        acc.z = fmaf(w2, b2.x, acc.z); acc.w = fmaf(w2, b2.y, acc.w);
        acc.x = fmaf(w3, a3.x, acc.x); acc.y = fmaf(w3, a3.y, acc.y);
        acc.z = fmaf(w3, b3.x, acc.z); acc.w = fmaf(w3, b3.y, acc.w);
    }
    for (; p < end; ++p) {
        int2 e0 = __ldg(g_colew + p);
        float w0 = __int_as_float(e0.y);
        uint2 v0 = __ldg((const uint2*)(Xl4 + e0.x));
        float2 a0 = __half22float2(*reinterpret_cast<__half2*>(&v0.x));
        float2 b0 = __half22float2(*reinterpret_cast<__half2*>(&v0.y));
        acc.x = fmaf(w0, a0.x, acc.x); acc.y = fmaf(w0, a0.y, acc.y);
        acc.z = fmaf(w0, b0.x, acc.z); acc.w = fmaf(w0, b0.y, acc.w);
    }

    uint2 hv, lv;
    split4(acc, hv, lv);
    size_t eo = (size_t)warp * D + lane * 4;
    if (mode == 0) {
        *(uint2*)(g_P116 + eo) = half4_of(acc);
        *(uint2*)(g_P1h + eo) = hv;
        *(uint2*)(g_P1l + eo) = lv;
    } else {
        *(uint2*)(g_P2h + eo) = hv;
        *(uint2*)(g_P2l + eo) = lv;
    }
}

// ======================= mma.sync bf16 GEMM (3-term split) =======================
// Y = relu(X0*W0' + P1*W1' + P2*W2' + b); all operands pre-split bf16 hi/lo.
// 8 warps, warp tile 64x32, m16n8k16. 6 chunks of K=64, double-buffered cp.async.
// Layers 0,1: emit fp16 + bf16 hi/lo. Layer 2: fused pred head -> logits only.

#define ROW_W     36
#define BUF_W     (128 * ROW_W)
#define BUF_BYTES (BUF_W * 4)             // 18432
#define CH_BYTES  (4 * BUF_BYTES)         // 73728 (Ah,Al,Bh,Bl)
#define GSMEM     (2 * CH_BYTES)          // 147456 dynamic smem

__device__ __forceinline__ void mma_bf16(float* acc,
                                         uint32_t a0, uint32_t a1, uint32_t a2, uint32_t a3,
                                         uint32_t b0, uint32_t b1) {
    asm volatile(
        "mma.sync.aligned.m16n8k16.row.col.f32.bf16.bf16.f32 "
        "{%0,%1,%2,%3}, {%4,%5,%6,%7}, {%8,%9}, {%0,%1,%2,%3};"
        : "+f"(acc[0]), "+f"(acc[1]), "+f"(acc[2]), "+f"(acc[3])
        : "r"(a0), "r"(a1), "r"(a2), "r"(a3), "r"(b0), "r"(b1));
}

__device__ __forceinline__ void issue_chunk(
    uint32_t bb,
    const __nv_bfloat16* __restrict__ Xh, const __nv_bfloat16* __restrict__ Xl,
    const __nv_bfloat16* __restrict__ WH, const __nv_bfloat16* __restrict__ WL,
    int row0, int kk, int kbase, int tid)
{
#pragma unroll
    for (int i = 0; i < 4; ++i) {
        int idx = tid + i * 256;
        int r = idx >> 3, f = idx & 7;
        int grow = row0 + r; if (grow >= NN) grow = NN - 1;
        CP16(bb + (uint32_t)(r * ROW_W + f * 4) * 4,
             Xh + (size_t)grow * D + kk + f * 8);
    }
#pragma unroll
    for (int i = 0; i < 4; ++i) {
        int idx = tid + i * 256;
        int r = idx >> 3, f = idx & 7;
        int grow = row0 + r; if (grow >= NN) grow = NN - 1;
        CP16(bb + BUF_BYTES + (uint32_t)(r * ROW_W + f * 4) * 4,
             Xl + (size_t)grow * D + kk + f * 8);
    }
#pragma unroll
    for (int i = 0; i < 4; ++i) {
        int idx = tid + i * 256;
        int n = idx >> 3, f = idx & 7;
        CP16(bb + 2 * BUF_BYTES + (uint32_t)(n * ROW_W + f * 4) * 4,
             WH + (size_t)n * 384 + kbase + f * 8);
    }
#pragma unroll
    for (int i = 0; i < 4; ++i) {
        int idx = tid + i * 256;
        int n = idx >> 3, f = idx & 7;
        CP16(bb + 3 * BUF_BYTES + (uint32_t)(n * ROW_W + f * 4) * 4,
             WL + (size_t)n * 384 + kbase + f * 8);
    }
}

__global__ __launch_bounds__(256, 1)
void gemm_mma_kernel(int layer, const float* __restrict__ bias, int flip,
                     const float* __restrict__ pw, const float* __restrict__ pb,
                     float* __restrict__ out) {
    extern __shared__ uint32_t dsm[];
    uint32_t sbase = (uint32_t)__cvta_generic_to_shared(dsm);

    const __nv_bfloat16* AH0 = g_Fh[flip];
    const __nv_bfloat16* AL0 = g_Fl[flip];
    __half*        Y16 = g_X16[flip ^ 1];
    __nv_bfloat16* Yh  = g_Fh[flip ^ 1];
    __nv_bfloat16* Yl  = g_Fl[flip ^ 1];
    const __nv_bfloat16* WH = g_Whi + (size_t)layer * 128 * 384;
    const __nv_bfloat16* WL = g_Wlo + (size_t)layer * 128 * 384;
    bool last = (layer == 2);

    int tid = threadIdx.x;
    int wid = tid >> 5;
    int lane = tid & 31;
    int g   = lane >> 2;
    int tig = lane & 3;
    int row0 = blockIdx.x * 128;

    int m0w = (wid >> 2) * 64;
    int n0w = (wid & 3) * 32;

    float acc[4][4][4];
#pragma unroll
    for (int mi = 0; mi < 4; ++mi)
#pragma unroll
        for (int ni = 0; ni < 4; ++ni)
#pragma unroll
            for (int q = 0; q < 4; ++q) acc[mi][ni][q] = 0.f;

    issue_chunk(sbase, AH0, AL0, WH, WL, row0, 0, 0, tid);
    CP_COMMIT();

    for (int c = 0; c < 6; ++c) {
        if (c < 5) {
            int nc = c + 1;
            int srcI = nc >> 1, kk = (nc & 1) * 64;
            const __nv_bfloat16* Xh = (srcI == 0) ? AH0 : ((srcI == 1) ? g_P1h : g_P2h);
            const __nv_bfloat16* Xl = (srcI == 0) ? AL0 : ((srcI == 1) ? g_P1l : g_P2l);
            issue_chunk(sbase + (uint32_t)(nc & 1) * CH_BYTES,
                        Xh, Xl, WH, WL, row0, kk, srcI * 128 + kk, tid);
            CP_COMMIT();
            CP_WAIT(1);
        } else {
            CP_WAIT(0);
        }
        __syncthreads();

        const uint32_t* Ah = dsm + (size_t)(c & 1) * (4 * BUF_W);
        const uint32_t* Al = Ah + BUF_W;
        const uint32_t* Bh = Ah + 2 * BUF_W;
        const uint32_t* Bl = Ah + 3 * BUF_W;

#pragma unroll
        for (int ks = 0; ks < 4; ++ks) {
            int kw = ks * 8;
            uint32_t ah[4][4], al[4][4], bh[4][2], bl[4][2];
#pragma unroll
            for (int mi = 0; mi < 4; ++mi) {
                const uint32_t* ph = Ah + (m0w + mi * 16 + g) * ROW_W + kw + tig;
                const uint32_t* pl = Al + (m0w + mi * 16 + g) * ROW_W + kw + tig;
                ah[mi][0] = ph[0];             al[mi][0] = pl[0];
                ah[mi][1] = ph[8 * ROW_W];     al[mi][1] = pl[8 * ROW_W];
                ah[mi][2] = ph[4];             al[mi][2] = pl[4];
                ah[mi][3] = ph[8 * ROW_W + 4]; al[mi][3] = pl[8 * ROW_W + 4];
            }
#pragma unroll
            for (int ni = 0; ni < 4; ++ni) {
                const uint32_t* ph = Bh + (n0w + ni * 8 + g) * ROW_W + kw + tig;
                const uint32_t* pl = Bl + (n0w + ni * 8 + g) * ROW_W + kw + tig;
                bh[ni][0] = ph[0]; bh[ni][1] = ph[4];
                bl[ni][0] = pl[0]; bl[ni][1] = pl[4];
            }
#pragma unroll
            for (int mi = 0; mi < 4; ++mi)
#pragma unroll
                for (int ni = 0; ni < 4; ++ni) {
                    mma_bf16(acc[mi][ni], ah[mi][0], ah[mi][1], ah[mi][2], ah[mi][3],
                             bh[ni][0], bh[ni][1]);
                    mma_bf16(acc[mi][ni], ah[mi][0], ah[mi][1], ah[mi][2], ah[mi][3],
                             bl[ni][0], bl[ni][1]);
                    mma_bf16(acc[mi][ni], al[mi][0], al[mi][1], al[mi][2], al[mi][3],
                             bh[ni][0], bh[ni][1]);
                }
        }
        __syncthreads();
    }

    if (!last) {
        // ---- epilogue: + bias, relu -> fp16 + bf16 hi/lo ----
#pragma unroll
        for (int mi = 0; mi < 4; ++mi) {
            int r0 = row0 + m0w + mi * 16 + g;
            int r1 = r0 + 8;
#pragma unroll
            for (int ni = 0; ni < 4; ++ni) {
                int c = n0w + ni * 8 + 2 * tig;
                float2 bb = *(const float2*)(bias + c);
                if (r0 < NN) {
                    float vx = fmaxf(acc[mi][ni][0] + bb.x, 0.f);
                    float vy = fmaxf(acc[mi][ni][1] + bb.y, 0.f);
                    __half2 q = __floats2half2_rn(vx, vy);
                    *(uint32_t*)(Y16 + (size_t)r0 * D + c) = *reinterpret_cast<uint32_t*>(&q);
                    __nv_bfloat16 h0 = __float2bfloat16_rn(vx);
                    __nv_bfloat16 h1 = __float2bfloat16_rn(vy);
                    *(uint32_t*)(Yh + (size_t)r0 * D + c) =
                        pack2(__bfloat162float(h0), __bfloat162float(h1));
                    *(uint32_t*)(Yl + (size_t)r0 * D + c) =
                        pack2(vx - __bfloat162float(h0), vy - __bfloat162float(h1));
                }
                if (r1 < NN) {
                    float vx = fmaxf(acc[mi][ni][2] + bb.x, 0.f);
                    float vy = fmaxf(acc[mi][ni][3] + bb.y, 0.f);
                    __half2 q = __floats2half2_rn(vx, vy);
                    *(uint32_t*)(Y16 + (size_t)r1 * D + c) = *reinterpret_cast<uint32_t*>(&q);
                    __nv_bfloat16 h0 = __float2bfloat16_rn(vx);
                    __nv_bfloat16 h1 = __float2bfloat16_rn(vy);
                    *(uint32_t*)(Yh + (size_t)r1 * D + c) =
                        pack2(__bfloat162float(h0), __bfloat162float(h1));
                    *(uint32_t*)(Yl + (size_t)r1 * D + c) =
                        pack2(vx - __bfloat162float(h0), vy - __bfloat162float(h1));
                }
            }
        }
    } else {
        // ---- fused prediction head: out[r] = relu(acc + b) . pw + pb ----
        float* red = (float*)dsm;          // 128 floats, smem now free
        if (tid < 128) red[tid] = 0.f;
        __syncthreads();
#pragma unroll
        for (int mi = 0; mi < 4; ++mi) {
            float p0 = 0.f, p1 = 0.f;
#pragma unroll
            for (int ni = 0; ni < 4; ++ni) {
                int c = n0w + ni * 8 + 2 * tig;
                float2 bb = *(const float2*)(bias + c);
                float2 pp = __ldg((const float2*)(pw + c));
                float vx = fmaxf(acc[mi][ni][0] + bb.x, 0.f);
                float vy = fmaxf(acc[mi][ni][1] + bb.y, 0.f);
                p0 += vx * pp.x + vy * pp.y;
                vx = fmaxf(acc[mi][ni][2] + bb.x, 0.f);
                vy = fmaxf(acc[mi][ni][3] + bb.y, 0.f);
                p1 += vx * pp.x + vy * pp.y;
            }
            atomicAdd(&red[m0w + mi * 16 + g], p0);
            atomicAdd(&red[m0w + mi * 16 + 8 + g], p1);
        }
        __syncthreads();
        if (tid < 128) {
            int r = row0 + tid;
            if (r < NN) out[r] = red[tid] + __ldg(pb);
        }
    }
}

// ---------------- host launch ----------------
extern "C" void kernel_launch(void* const* d_in, const int* in_sizes, int n_in,
                              void* d_out, int out_size) {
    const float* weights = (const float*)d_in[0];
    const int*   src     = (const int*)d_in[1];
    const int*   dst     = (const int*)d_in[2];
    const float* lin_w   = (const float*)d_in[3];
    const float* lin_b   = (const float*)d_in[4];
    const float* cheb_ws = (const float*)d_in[5];
    const float* cheb_bs = (const float*)d_in[6];
    const float* pred_w  = (const float*)d_in[7];
    const float* pred_b  = (const float*)d_in[8];
    float* out = (float*)d_out;

    cudaFuncSetAttribute(gemm_mma_kernel,
                         cudaFuncAttributeMaxDynamicSharedMemorySize, GSMEM);
    cudaFuncSetAttribute(scan_kernel,
                         cudaFuncAttributeMaxDynamicSharedMemorySize, NN * 4);

    // fused count | feat | wprep, then scan, then scatter
    prep_kernel   <<<NB_PREP, 256>>>(dst, weights, lin_w, lin_b, cheb_ws);
    scan_kernel   <<<1, 1024, NN * 4>>>();
    scatter_kernel<<<(NT + 255) / 256, 256>>>(src, dst);

    const int spmm_blocks = (NN * 32 + 255) / 256;   // one warp per node
    const int gemm_blocks = (NN + 127) / 128;        // 391

    for (int l = 0; l < 3; ++l) {
        int flip = l & 1;
        spmm_kernel<<<spmm_blocks, 256>>>(0, flip);   // P1 = A~ X0
        spmm_kernel<<<spmm_blocks, 256>>>(1, flip);   // P2 = A~ P1
        gemm_mma_kernel<<<gemm_blocks, 256, GSMEM>>>(
            l, cheb_bs + (size_t)l * 128, flip, pred_w, pred_b, out);
        // inter-layer leaky_relu(relu(x)) == relu(x): no-op, skipped
    }
}

// round 14
// speedup vs baseline: 1.5490x; 1.2806x over previous
#include <cuda_runtime.h>
#include <cuda_bf16.h>
#include <cuda_fp16.h>
#include <cstdint>

#define NN   50000
#define NE   600000
#define NT   (NE + NN)     // edges + self loops = 650000
#define D    128

// ---------------- device scratch (static, no runtime alloc) ----------------
// All features live as fp16 (both SpMM gather and GEMM A operand).
__device__ __half g_X16[2][(size_t)NN * D];
__device__ __half g_P116[(size_t)NN * D];
__device__ __half g_P216[(size_t)NN * D];
__device__ int2  g_colew[NT];            // packed {col*D, bitcast(weight)}
__device__ int   g_rowptr[NN + 1];
__device__ int   g_deg[NN];              // zero-init at load; scan self-resets
__device__ int   g_epos[NE];             // per-edge slot within its row
__device__ float g_dinv[NN];
// Folded W (W0-W2, -W1, 2*W2) as fp16 hi/lo, transposed: [layer][n(128)][k(384)]
// w = wh + wl with wh=fp16(w), wl=fp16(w-wh): covers fp32 W to ~2^-22.
__device__ __half g_Wh16[3 * 128 * 384];
__device__ __half g_Wl16[3 * 128 * 384];

// ---------------- helpers ----------------
__device__ __forceinline__ uint2 half4_of(float4 v) {
    __half2 q01 = __floats2half2_rn(v.x, v.y);
    __half2 q23 = __floats2half2_rn(v.z, v.w);
    return make_uint2(*reinterpret_cast<uint32_t*>(&q01),
                      *reinterpret_cast<uint32_t*>(&q23));
}

#define CP16(daddr, gptr) \
    asm volatile("cp.async.cg.shared.global [%0], [%1], 16;" \
        :: "r"(daddr), "l"(gptr))
#define CP_COMMIT() asm volatile("cp.async.commit_group;" ::: "memory")
#define CP_WAIT(n)  asm volatile("cp.async.wait_group %0;" :: "n"(n) : "memory")

// ---------------- fused prep: count degrees (+slot) | input linear | W fold ----
#define NB_COUNT ((NE + 255) / 256)               // 2344
#define NB_FEAT  ((NN * (D / 4) + 255) / 256)     // 6250
#define NB_WPREP ((3 * 384 * 128 + 255) / 256)    // 576
#define NB_PREP  (NB_COUNT + NB_FEAT + NB_WPREP)

__global__ void prep_kernel(const int* __restrict__ dst,
                            const float* __restrict__ w,
                            const float* __restrict__ lw,
                            const float* __restrict__ lb,
                            const float* __restrict__ cheb_ws) {
    int b = blockIdx.x;
    int tid = threadIdx.x;
    if (b < NB_COUNT) {
        int e = b * 256 + tid;
        if (e < NE) g_epos[e] = atomicAdd(&g_deg[dst[e]], 1);
    } else if (b < NB_COUNT + NB_FEAT) {
        int i = (b - NB_COUNT) * 256 + tid;
        if (i >= NN * (D / 4)) return;
        int v  = i >> 5;
        int d4 = i & 31;
        float s = __ldg(w + v);
        float4 a = __ldg((const float4*)lw + d4);
        float4 bb = __ldg((const float4*)lb + d4);
        float4 r;
        r.x = fmaf(s, a.x, bb.x); r.y = fmaf(s, a.y, bb.y);
        r.z = fmaf(s, a.z, bb.z); r.w = fmaf(s, a.w, bb.w);
        *(uint2*)(g_X16[0] + (size_t)i * 4) = half4_of(r);
    } else {
        int i = (b - NB_COUNT - NB_FEAT) * 256 + tid;
        if (i >= 3 * 384 * 128) return;
        int l   = i / (384 * 128);
        int rem = i % (384 * 128);
        int k = rem >> 7;
        int n = rem & 127;
        int seg = k >> 7;
        int kin = k & 127;
        const float* WL0 = cheb_ws + (size_t)l * 384 * 128;
        float wv;
        if (seg == 0)      wv = __ldg(WL0 + (size_t)k * 128 + n) - __ldg(WL0 + (size_t)(256 + kin) * 128 + n);
        else if (seg == 1) wv = -__ldg(WL0 + (size_t)k * 128 + n);
        else               wv = 2.0f * __ldg(WL0 + (size_t)k * 128 + n);
        __half h = __float2half_rn(wv);
        size_t o = ((size_t)l * 128 + n) * 384 + k;
        g_Wh16[o] = h;
        g_Wl16[o] = __float2half_rn(wv - __half2float(h));
    }
}

// ---------------- CSR: single-block scan (smem-staged, self-resetting) --------
__global__ void scan_kernel() {
    extern __shared__ int ssm[];            // NN ints
    __shared__ int part[1024];
    const int T = 1024;
    const int CHUNK = (NN + T - 1) / T;     // 49
    int tid = threadIdx.x;

    for (int i = tid; i < NN; i += T) {
        ssm[i] = g_deg[i] + 1;              // +1 self loop
        g_deg[i] = 0;
    }
    __syncthreads();

    int start = tid * CHUNK;
    int end = start + CHUNK; if (end > NN) end = NN;
    int s = 0;
    for (int i = start; i < end; ++i) s += ssm[i];
    part[tid] = s;
    __syncthreads();
    for (int off = 1; off < T; off <<= 1) {
        int v = (tid >= off) ? part[tid - off] : 0;
        __syncthreads();
        part[tid] += v;
        __syncthreads();
    }
    int run = part[tid] - s;
    for (int i = start; i < end; ++i) {
        int v = ssm[i];
        ssm[i] = run;
        run += v;
    }
    __syncthreads();
    int total = part[T - 1];
    for (int i = tid; i < NN; i += T) {
        int rp = ssm[i];
        g_rowptr[i] = rp;
        int nxt = (i + 1 < NN) ? ssm[i + 1] : total;
        g_dinv[i] = rsqrtf((float)(nxt - rp));
    }
    if (tid == 0) g_rowptr[NN] = total;
}

__global__ void scatter_kernel(const int* __restrict__ src, const int* __restrict__ dst) {
    int e = blockIdx.x * blockDim.x + threadIdx.x;
    if (e >= NT) return;
    int s, d, pos;
    if (e < NE) {
        s = src[e]; d = dst[e];
        pos = g_rowptr[d] + g_epos[e];
    } else {
        s = d = e - NE;
        pos = g_rowptr[d + 1] - 1;           // self loop takes the last slot
    }
    g_colew[pos] = make_int2(s * D, __float_as_int(g_dinv[s] * g_dinv[d]));
}

// ---------------- SpMM: out = A_norm @ X (fp16 gather, fp16-only writes) -------
__global__ __launch_bounds__(256, 7)
void spmm_kernel(int mode, int flip) {
    const __half* __restrict__ X = (mode == 0) ? g_X16[flip] : g_P116;
    __half* __restrict__ OUT = (mode == 0) ? g_P116 : g_P216;

    int warp = (blockIdx.x * blockDim.x + threadIdx.x) >> 5;
    if (warp >= NN) return;
    int lane = threadIdx.x & 31;
    int beg = g_rowptr[warp];
    int end = g_rowptr[warp + 1];

    const __half* Xl4 = X + lane * 4;      // lane-fixed base; edge offset pre-scaled

    float4 acc = make_float4(0.f, 0.f, 0.f, 0.f);
    int p = beg;
    for (; p + 3 < end; p += 4) {
        int2 e0 = __ldg(g_colew + p);
        int2 e1 = __ldg(g_colew + p + 1);
        int2 e2 = __ldg(g_colew + p + 2);
        int2 e3 = __ldg(g_colew + p + 3);
        uint2 v0 = __ldg((const uint2*)(Xl4 + e0.x));
        uint2 v1 = __ldg((const uint2*)(Xl4 + e1.x));
        uint2 v2 = __ldg((const uint2*)(Xl4 + e2.x));
        uint2 v3 = __ldg((const uint2*)(Xl4 + e3.x));
        float w0 = __int_as_float(e0.y);
        float w1 = __int_as_float(e1.y);
        float w2 = __int_as_float(e2.y);
        float w3 = __int_as_float(e3.y);
        float2 a0 = __half22float2(*reinterpret_cast<__half2*>(&v0.x));
        float2 b0 = __half22float2(*reinterpret_cast<__half2*>(&v0.y));
        float2 a1 = __half22float2(*reinterpret_cast<__half2*>(&v1.x));
        float2 b1 = __half22float2(*reinterpret_cast<__half2*>(&v1.y));
        float2 a2 = __half22float2(*reinterpret_cast<__half2*>(&v2.x));
        float2 b2 = __half22float2(*reinterpret_cast<__half2*>(&v2.y));
        float2 a3 = __half22float2(*reinterpret_cast<__half2*>(&v3.x));
        float2 b3 = __half22float2(*reinterpret_cast<__half2*>(&v3.y));
        acc.x = fmaf(w0, a0.x, acc.x); acc.y = fmaf(w0, a0.y, acc.y);
        acc.z = fmaf(w0, b0.x, acc.z); acc.w = fmaf(w0, b0.y, acc.w);
        acc.x = fmaf(w1, a1.x, acc.x); acc.y = fmaf(w1, a1.y, acc.y);
        acc.z = fmaf(w1, b1.x, acc.z); acc.w = fmaf(w1, b1.y, acc.w);
        acc.x = fmaf(w2, a2.x, acc.x); acc.y = fmaf(w2, a2.y, acc.y);
        acc.z = fmaf(w2, b2.x, acc.z); acc.w = fmaf(w2, b2.y, acc.w);
        acc.x = fmaf(w3, a3.x, acc.x); acc.y = fmaf(w3, a3.y, acc.y);
        acc.z = fmaf(w3, b3.x, acc.z); acc.w = fmaf(w3, b3.y, acc.w);
    }
    for (; p < end; ++p) {
        int2 e0 = __ldg(g_colew + p);
        float w0 = __int_as_float(e0.y);
        uint2 v0 = __ldg((const uint2*)(Xl4 + e0.x));
        float2 a0 = __half22float2(*reinterpret_cast<__half2*>(&v0.x));
        float2 b0 = __half22float2(*reinterpret_cast<__half2*>(&v0.y));
        acc.x = fmaf(w0, a0.x, acc.x); acc.y = fmaf(w0, a0.y, acc.y);
        acc.z = fmaf(w0, b0.x, acc.z); acc.w = fmaf(w0, b0.y, acc.w);
    }

    *(uint2*)(OUT + (size_t)warp * D + lane * 4) = half4_of(acc);
}

// ======================= mma.sync fp16 GEMM (W hi/lo split) =====================
// Y = relu(X0*W0' + P1*W1' + P2*W2' + b).
// A is the stored fp16 feature (no extra error beyond fp16 storage);
// W = Wh + Wl fp16 pair (covers fp32 to 2^-22). 2 MMA terms: A*Wh + A*Wl.
// 8 warps, warp tile 64x32, m16n8k16.f16. 6 chunks K=64, double-buffered cp.async.

#define ROW_W     36
#define BUF_W     (128 * ROW_W)
#define BUF_BYTES (BUF_W * 4)             // 18432
#define CH_BYTES  (3 * BUF_BYTES)         // 55296 (A, Bh, Bl)
#define GSMEM     (2 * CH_BYTES)          // 110592 dynamic smem

__device__ __forceinline__ void mma_f16(float* acc,
                                        uint32_t a0, uint32_t a1, uint32_t a2, uint32_t a3,
                                        uint32_t b0, uint32_t b1) {
    asm volatile(
        "mma.sync.aligned.m16n8k16.row.col.f32.f16.f16.f32 "
        "{%0,%1,%2,%3}, {%4,%5,%6,%7}, {%8,%9}, {%0,%1,%2,%3};"
        : "+f"(acc[0]), "+f"(acc[1]), "+f"(acc[2]), "+f"(acc[3])
        : "r"(a0), "r"(a1), "r"(a2), "r"(a3), "r"(b0), "r"(b1));
}

__device__ __forceinline__ void issue_chunk(
    uint32_t bb,
    const __half* __restrict__ X,
    const __half* __restrict__ WH, const __half* __restrict__ WL,
    int row0, int kk, int kbase, int tid)
{
    // A: 128 rows x 64 fp16 (128B) = 8 x 16B per row -> 1024 cp
#pragma unroll
    for (int i = 0; i < 4; ++i) {
        int idx = tid + i * 256;
        int r = idx >> 3, f = idx & 7;
        int grow = row0 + r; if (grow >= NN) grow = NN - 1;   // OOB rows discarded later
        CP16(bb + (uint32_t)(r * ROW_W + f * 4) * 4,
             X + (size_t)grow * D + kk + f * 8);
    }
    // Bh, Bl: 128 n-rows x 64 fp16 each
#pragma unroll
    for (int i = 0; i < 4; ++i) {
        int idx = tid + i * 256;
        int n = idx >> 3, f = idx & 7;
        CP16(bb + BUF_BYTES + (uint32_t)(n * ROW_W + f * 4) * 4,
             WH + (size_t)n * 384 + kbase + f * 8);
    }
#pragma unroll
    for (int i = 0; i < 4; ++i) {
        int idx = tid + i * 256;
        int n = idx >> 3, f = idx & 7;
        CP16(bb + 2 * BUF_BYTES + (uint32_t)(n * ROW_W + f * 4) * 4,
             WL + (size_t)n * 384 + kbase + f * 8);
    }
}

__global__ __launch_bounds__(256, 1)
void gemm_mma_kernel(int layer, const float* __restrict__ bias, int flip,
                     const float* __restrict__ pw, const float* __restrict__ pb,
                     float* __restrict__ out) {
    extern __shared__ uint32_t dsm[];
    uint32_t sbase = (uint32_t)__cvta_generic_to_shared(dsm);

    const __half* A0 = g_X16[flip];
    __half*       Y16 = g_X16[flip ^ 1];
    const __half* WH = g_Wh16 + (size_t)layer * 128 * 384;
    const __half* WL = g_Wl16 + (size_t)layer * 128 * 384;
    bool last = (layer == 2);

    int tid = threadIdx.x;
    int wid = tid >> 5;
    int lane = tid & 31;
    int g   = lane >> 2;
    int tig = lane & 3;
    int row0 = blockIdx.x * 128;

    int m0w = (wid >> 2) * 64;
    int n0w = (wid & 3) * 32;

    float acc[4][4][4];
#pragma unroll
    for (int mi = 0; mi < 4; ++mi)
#pragma unroll
        for (int ni = 0; ni < 4; ++ni)
#pragma unroll
            for (int q = 0; q < 4; ++q) acc[mi][ni][q] = 0.f;

    issue_chunk(sbase, A0, WH, WL, row0, 0, 0, tid);
    CP_COMMIT();

    for (int c = 0; c < 6; ++c) {
        if (c < 5) {
            int nc = c + 1;
            int srcI = nc >> 1, kk = (nc & 1) * 64;
            const __half* X = (srcI == 0) ? A0 : ((srcI == 1) ? g_P116 : g_P216);
            issue_chunk(sbase + (uint32_t)(nc & 1) * CH_BYTES,
                        X, WH, WL, row0, kk, srcI * 128 + kk, tid);
            CP_COMMIT();
            CP_WAIT(1);
        } else {
            CP_WAIT(0);
        }
        __syncthreads();

        const uint32_t* As = dsm + (size_t)(c & 1) * (3 * BUF_W);
        const uint32_t* Bh = As + BUF_W;
        const uint32_t* Bl = As + 2 * BUF_W;

#pragma unroll
        for (int ks = 0; ks < 4; ++ks) {
            int kw = ks * 8;
            uint32_t af[4][4], bh[4][2], bl[4][2];
#pragma unroll
            for (int mi = 0; mi < 4; ++mi) {
                const uint32_t* pa = As + (m0w + mi * 16 + g) * ROW_W + kw + tig;
                af[mi][0] = pa[0];
                af[mi][1] = pa[8 * ROW_W];
                af[mi][2] = pa[4];
                af[mi][3] = pa[8 * ROW_W + 4];
            }
#pragma unroll
            for (int ni = 0; ni < 4; ++ni) {
                const uint32_t* ph = Bh + (n0w + ni * 8 + g) * ROW_W + kw + tig;
                const uint32_t* pl = Bl + (n0w + ni * 8 + g) * ROW_W + kw + tig;
                bh[ni][0] = ph[0]; bh[ni][1] = ph[4];
                bl[ni][0] = pl[0]; bl[ni][1] = pl[4];
            }
#pragma unroll
            for (int mi = 0; mi < 4; ++mi)
#pragma unroll
                for (int ni = 0; ni < 4; ++ni) {
                    mma_f16(acc[mi][ni], af[mi][0], af[mi][1], af[mi][2], af[mi][3],
                            bh[ni][0], bh[ni][1]);
                    mma_f16(acc[mi][ni], af[mi][0], af[mi][1], af[mi][2], af[mi][3],
                            bl[ni][0], bl[ni][1]);
                }
        }
        __syncthreads();
    }

    if (!last) {
        // ---- epilogue: + bias, relu -> fp16 only ----
#pragma unroll
        for (int mi = 0; mi < 4; ++mi) {
            int r0 = row0 + m0w + mi * 16 + g;
            int r1 = r0 + 8;
#pragma unroll
            for (int ni = 0; ni < 4; ++ni) {
                int c = n0w + ni * 8 + 2 * tig;
                float2 bb = *(const float2*)(bias + c);
                if (r0 < NN) {
                    float vx = fmaxf(acc[mi][ni][0] + bb.x, 0.f);
                    float vy = fmaxf(acc[mi][ni][1] + bb.y, 0.f);
                    __half2 q = __floats2half2_rn(vx, vy);
                    *(uint32_t*)(Y16 + (size_t)r0 * D + c) = *reinterpret_cast<uint32_t*>(&q);
                }
                if (r1 < NN) {
                    float vx = fmaxf(acc[mi][ni][2] + bb.x, 0.f);
                    float vy = fmaxf(acc[mi][ni][3] + bb.y, 0.f);
                    __half2 q = __floats2half2_rn(vx, vy);
                    *(uint32_t*)(Y16 + (size_t)r1 * D + c) = *reinterpret_cast<uint32_t*>(&q);
                }
            }
        }
    } else {
        // ---- fused prediction head: out[r] = relu(acc + b) . pw + pb ----
        float* red = (float*)dsm;          // 128 floats, smem now free
        if (tid < 128) red[tid] = 0.f;
        __syncthreads();
#pragma unroll
        for (int mi = 0; mi < 4; ++mi) {
            float p0 = 0.f, p1 = 0.f;
#pragma unroll
            for (int ni = 0; ni < 4; ++ni) {
                int c = n0w + ni * 8 + 2 * tig;
                float2 bb = *(const float2*)(bias + c);
                float2 pp = __ldg((const float2*)(pw + c));
                float vx = fmaxf(acc[mi][ni][0] + bb.x, 0.f);
                float vy = fmaxf(acc[mi][ni][1] + bb.y, 0.f);
                p0 += vx * pp.x + vy * pp.y;
                vx = fmaxf(acc[mi][ni][2] + bb.x, 0.f);
                vy = fmaxf(acc[mi][ni][3] + bb.y, 0.f);
                p1 += vx * pp.x + vy * pp.y;
            }
            atomicAdd(&red[m0w + mi * 16 + g], p0);
            atomicAdd(&red[m0w + mi * 16 + 8 + g], p1);
        }
        __syncthreads();
        if (tid < 128) {
            int r = row0 + tid;
            if (r < NN) out[r] = red[tid] + __ldg(pb);
        }
    }
}

// ---------------- host launch ----------------
extern "C" void kernel_launch(void* const* d_in, const int* in_sizes, int n_in,
                              void* d_out, int out_size) {
    const float* weights = (const float*)d_in[0];
    const int*   src     = (const int*)d_in[1];
    const int*   dst     = (const int*)d_in[2];
    const float* lin_w   = (const float*)d_in[3];
    const float* lin_b   = (const float*)d_in[4];
    const float* cheb_ws = (const float*)d_in[5];
    const float* cheb_bs = (const float*)d_in[6];
    const float* pred_w  = (const float*)d_in[7];
    const float* pred_b  = (const float*)d_in[8];
    float* out = (float*)d_out;

    cudaFuncSetAttribute(gemm_mma_kernel,
                         cudaFuncAttributeMaxDynamicSharedMemorySize, GSMEM);
    cudaFuncSetAttribute(scan_kernel,
                         cudaFuncAttributeMaxDynamicSharedMemorySize, NN * 4);

    // fused count | feat | wprep, then scan, then scatter
    prep_kernel   <<<NB_PREP, 256>>>(dst, weights, lin_w, lin_b, cheb_ws);
    scan_kernel   <<<1, 1024, NN * 4>>>();
    scatter_kernel<<<(NT + 255) / 256, 256>>>(src, dst);

    const int spmm_blocks = (NN * 32 + 255) / 256;   // one warp per node
    const int gemm_blocks = (NN + 127) / 128;        // 391

    for (int l = 0; l < 3; ++l) {
        int flip = l & 1;
        spmm_kernel<<<spmm_blocks, 256>>>(0, flip);   // P1 = A~ X0
        spmm_kernel<<<spmm_blocks, 256>>>(1, flip);   // P2 = A~ P1
        gemm_mma_kernel<<<gemm_blocks, 256, GSMEM>>>(
            l, cheb_bs + (size_t)l * 128, flip, pred_w, pred_b, out);
        // inter-layer leaky_relu(relu(x)) == relu(x): no-op, skipped
    }
}